// round 1
// baseline (speedup 1.0000x reference)
#include <cuda_runtime.h>
#include <math.h>

#define E_EXPERTS 5
#define CDIM      256
#define HALF      128
#define QUART     64
#define BDIM      8
#define NPIX      6400
#define PIX       32

typedef unsigned long long u64;

__device__ int   g_expert[BDIM];
__device__ float g_pooled[BDIM * CDIM];

// ---------- packed f32x2 helpers ----------
__device__ __forceinline__ u64 pack2(float a, float b) {
    u64 r; asm("mov.b64 %0,{%1,%2};" : "=l"(r) : "f"(a), "f"(b)); return r;
}
__device__ __forceinline__ float2 unpack2(u64 v) {
    float2 f; asm("mov.b64 {%0,%1},%2;" : "=f"(f.x), "=f"(f.y) : "l"(v)); return f;
}
__device__ __forceinline__ u64 fma2(u64 a, u64 b, u64 c) {
    u64 d; asm("fma.rn.f32x2 %0,%1,%2,%3;" : "=l"(d) : "l"(a), "l"(b), "l"(c)); return d;
}
__device__ __forceinline__ u64 add2(u64 a, u64 b) {
    u64 d; asm("add.rn.f32x2 %0,%1,%2;" : "=l"(d) : "l"(a), "l"(b)); return d;
}

// ---------- gate kernel 1: pooled[b][c] = mean over 6400 pixels ----------
__global__ void __launch_bounds__(256) gate_pool(const float* __restrict__ x) {
    int bc = blockIdx.x;                       // b*256 + c
    const float* p = x + (size_t)bc * NPIX;
    float s = 0.f;
    for (int i = threadIdx.x; i < NPIX; i += 256) s += p[i];
    __shared__ float red[32];
    #pragma unroll
    for (int o = 16; o; o >>= 1) s += __shfl_down_sync(0xffffffffu, s, o);
    if ((threadIdx.x & 31) == 0) red[threadIdx.x >> 5] = s;
    __syncthreads();
    if (threadIdx.x < 32) {
        float v = (threadIdx.x < 8) ? red[threadIdx.x] : 0.f;
        #pragma unroll
        for (int o = 4; o; o >>= 1) v += __shfl_down_sync(0xffffffffu, v, o);
        if (threadIdx.x == 0) g_pooled[bc] = v * (1.0f / (float)NPIX);
    }
}

// ---------- gate kernel 2: argmax expert per batch (one-hot softmax == select top1) ----------
__global__ void __launch_bounds__(256) gate_select(const float* __restrict__ Wg,
                                                   const float* __restrict__ bg) {
    int w = threadIdx.x >> 5, lane = threadIdx.x & 31;
    if (w >= BDIM) return;
    float best = -1e30f; int bi = 0;
    for (int e = 0; e < E_EXPERTS; e++) {
        float s = 0.f;
        for (int c = lane; c < CDIM; c += 32) s += g_pooled[w * CDIM + c] * Wg[e * CDIM + c];
        #pragma unroll
        for (int o = 16; o; o >>= 1) s += __shfl_down_sync(0xffffffffu, s, o);
        s += bg[e];
        s = __shfl_sync(0xffffffffu, s, 0);
        if (s > best) { best = s; bi = e; }   // strict > keeps first max (argmax semantics)
    }
    if (lane == 0) g_expert[w] = bi;
}

// ---------- smem layout (floats) ----------
// sWr : 128*129 = 16512   (Wrgb^T, pad 129: conflict-free load & store)
// sWt : 128*129 = 16512   (Wtir^T)
// sW1 : 128*65  =  8320   (Wt1^T, pad 65)
// sX  : 256*32  =  8192   (x tile; reused after GEMM1 as sH[2][32*65]=4160 + sA[64])
// sD  : 2*128*32 = 8192   (pixel-pair u64: sD[br*2048 + p2*128 + o])
// total floats 57728 -> 230912 bytes (< 232448 max dynamic)
#define SWR_OFF 0
#define SWT_OFF 16512
#define SW1_OFF 33024
#define SX_OFF  41344
#define SD_OFF  49536
#define SMEM_FLOATS 57728
#define SMEM_BYTES  (SMEM_FLOATS * 4)

__global__ void __launch_bounds__(256, 1) moe_expert(
    const float* __restrict__ x,
    const float* __restrict__ Wrgb, const float* __restrict__ brgb,
    const float* __restrict__ Wtir, const float* __restrict__ btir,
    const float* __restrict__ Wt1,  const float* __restrict__ bt1,
    const float* __restrict__ Wt2,  const float* __restrict__ bt2,
    float* __restrict__ out)
{
    extern __shared__ float sm[];
    float* sWr = sm + SWR_OFF;
    float* sWt = sm + SWT_OFF;
    float* sW1 = sm + SW1_OFF;
    float* sX  = sm + SX_OFF;
    float* sH  = sX;                     // reuse after GEMM1 (2*32*65 = 4160 floats)
    float* sA  = sX + 4160;              // 64 floats
    u64*   sD  = (u64*)(sm + SD_OFF);    // [2][16 pairs][128 o]

    const int t    = threadIdx.x;
    const int b    = blockIdx.y;
    const int pix0 = blockIdx.x * PIX;
    const int e    = g_expert[b];

    // ---------------- prologue: stage weights + x tile ----------------
    {
        const float* gWr = Wrgb + e * HALF * HALF;
        const float* gWt = Wtir + e * HALF * HALF;
        #pragma unroll 4
        for (int k = 0; k < 64; k++) {
            int lin = k * 256 + t;           // lin = o*128 + c
            int o = lin >> 7, c = lin & 127;
            sWr[c * 129 + o] = gWr[lin];
            sWt[c * 129 + o] = gWt[lin];
        }
        const float* gW1 = Wt1 + e * QUART * HALF;
        #pragma unroll 4
        for (int k = 0; k < 32; k++) {
            int lin = k * 256 + t;           // lin = m*128 + o
            int m = lin >> 7, o = lin & 127;
            sW1[o * 65 + m] = gW1[lin];
        }
        const float* gX = x + (size_t)b * CDIM * NPIX + pix0;
        #pragma unroll
        for (int k = 0; k < 8; k++) {
            int lin = k * 256 + t;           // float4 index
            int c = lin >> 3, j = lin & 7;
            *(float4*)(sX + c * 32 + j * 4) =
                *(const float4*)(gX + (size_t)c * NPIX + j * 4);
        }
    }
    __syncthreads();

    // ---------------- GEMM1: Dr/Dt = x + W @ x + b (packed f32x2, 2 pixel-halves) ----
    const int o  = t & 127;       // output channel
    const int ph = t >> 7;        // pixel half: 16 pixels = 8 pairs

    u64 aR[8], aT[8];
    #pragma unroll
    for (int j = 0; j < 8; j++) { aR[j] = 0ull; aT[j] = 0ull; }

    const ulonglong2* sX2 = (const ulonglong2*)sX;  // row c -> index c*8 .. c*8+7
    #pragma unroll 4
    for (int c = 0; c < 128; c++) {
        const u64 wr2 = pack2(sWr[c * 129 + o], sWr[c * 129 + o]);
        const u64 wt2 = pack2(sWt[c * 129 + o], sWt[c * 129 + o]);
        const ulonglong2* xr = sX2 + c * 8 + ph * 4;
        const ulonglong2* xt = sX2 + (128 + c) * 8 + ph * 4;
        #pragma unroll
        for (int k = 0; k < 4; k++) {
            ulonglong2 v = xr[k];
            aR[2 * k]     = fma2(v.x, wr2, aR[2 * k]);
            aR[2 * k + 1] = fma2(v.y, wr2, aR[2 * k + 1]);
        }
        #pragma unroll
        for (int k = 0; k < 4; k++) {
            ulonglong2 v = xt[k];
            aT[2 * k]     = fma2(v.x, wt2, aT[2 * k]);
            aT[2 * k + 1] = fma2(v.y, wt2, aT[2 * k + 1]);
        }
    }

    // epilogue: + residual + bias; keep in regs AND stage to sD for GEMM2
    u64 dR[8], dT[8];
    {
        float brv = __ldg(brgb + e * HALF + o);
        float btv = __ldg(btir + e * HALF + o);
        u64 br2 = pack2(brv, brv), bt2p = pack2(btv, btv);
        const ulonglong2* xro = sX2 + o * 8 + ph * 4;
        const ulonglong2* xto = sX2 + (128 + o) * 8 + ph * 4;
        #pragma unroll
        for (int k = 0; k < 4; k++) {
            ulonglong2 vr = xro[k];
            ulonglong2 vt = xto[k];
            dR[2 * k]     = add2(add2(aR[2 * k],     vr.x), br2);
            dR[2 * k + 1] = add2(add2(aR[2 * k + 1], vr.y), br2);
            dT[2 * k]     = add2(add2(aT[2 * k],     vt.x), bt2p);
            dT[2 * k + 1] = add2(add2(aT[2 * k + 1], vt.y), bt2p);
        }
        #pragma unroll
        for (int j = 0; j < 8; j++) {
            sD[(ph * 8 + j) * 128 + o]        = dR[j];
            sD[2048 + (ph * 8 + j) * 128 + o] = dT[j];
        }
    }
    __syncthreads();

    // ---------------- GEMM2: h[m][p] = relu(Wt1 @ D + bt1) ----------------
    {
        const int m = t & 63;
        const int q = t >> 6;                 // pair range q*4 .. q*4+3 (8 pixels)
        u64 hR[4], hT[4];
        #pragma unroll
        for (int j = 0; j < 4; j++) { hR[j] = 0ull; hT[j] = 0ull; }

        #pragma unroll 4
        for (int o2 = 0; o2 < 128; o2++) {
            float w1 = sW1[o2 * 65 + m];
            u64 w12 = pack2(w1, w1);
            #pragma unroll
            for (int j = 0; j < 4; j++) {
                hR[j] = fma2(sD[(q * 4 + j) * 128 + o2],        w12, hR[j]);
                hT[j] = fma2(sD[2048 + (q * 4 + j) * 128 + o2], w12, hT[j]);
            }
        }
        float b1 = __ldg(bt1 + e * QUART + m);
        #pragma unroll
        for (int j = 0; j < 4; j++) {
            float2 fr = unpack2(hR[j]);
            float2 ft = unpack2(hT[j]);
            int p = q * 8 + 2 * j;
            sH[p * 65 + m]             = fmaxf(fr.x + b1, 0.f);
            sH[(p + 1) * 65 + m]       = fmaxf(fr.y + b1, 0.f);
            sH[2080 + p * 65 + m]       = fmaxf(ft.x + b1, 0.f);
            sH[2080 + (p + 1) * 65 + m] = fmaxf(ft.y + b1, 0.f);
        }
    }
    __syncthreads();

    // ---------------- attention scalars: a[br][p] = sigmoid(Wt2 . h + bt2) ----------
    if (t < 64) {
        int br = t >> 5, p = t & 31;
        const float* hh = sH + br * 2080 + p * 65;
        const float* w2 = Wt2 + e * QUART;
        float s = __ldg(bt2 + e);
        #pragma unroll
        for (int m2 = 0; m2 < 64; m2++) s += hh[m2] * __ldg(w2 + m2);
        sA[br * 32 + p] = 1.f / (1.f + expf(-s));
    }
    __syncthreads();

    // ---------------- fused output from registers ----------------
    {
        float* go = out + ((size_t)(b * HALF + o)) * NPIX + pix0 + ph * 16;
        #pragma unroll
        for (int j = 0; j < 4; j++) {
            int p = ph * 16 + 4 * j;
            float2 r0 = unpack2(dR[2 * j]), r1 = unpack2(dR[2 * j + 1]);
            float2 t0 = unpack2(dT[2 * j]), t1 = unpack2(dT[2 * j + 1]);
            float4 v;
            v.x = sA[p]     * r0.x + sA[32 + p]     * t0.x;
            v.y = sA[p + 1] * r0.y + sA[32 + p + 1] * t0.y;
            v.z = sA[p + 2] * r1.x + sA[32 + p + 2] * t1.x;
            v.w = sA[p + 3] * r1.y + sA[32 + p + 3] * t1.y;
            *(float4*)(go + 4 * j) = v;
        }
    }
}

extern "C" void kernel_launch(void* const* d_in, const int* in_sizes, int n_in,
                              void* d_out, int out_size) {
    const float* x    = (const float*)d_in[0];
    const float* Wg   = (const float*)d_in[1];
    const float* bg   = (const float*)d_in[2];
    const float* Wrgb = (const float*)d_in[3];
    const float* brgb = (const float*)d_in[4];
    const float* Wtir = (const float*)d_in[5];
    const float* btir = (const float*)d_in[6];
    const float* Wt1  = (const float*)d_in[7];
    const float* bt1  = (const float*)d_in[8];
    const float* Wt2  = (const float*)d_in[9];
    const float* bt2  = (const float*)d_in[10];
    float* out = (float*)d_out;

    gate_pool<<<BDIM * CDIM, 256>>>(x);
    gate_select<<<1, 256>>>(Wg, bg);

    cudaFuncSetAttribute(moe_expert, cudaFuncAttributeMaxDynamicSharedMemorySize, SMEM_BYTES);
    dim3 grid(NPIX / PIX, BDIM);
    moe_expert<<<grid, 256, SMEM_BYTES>>>(x, Wrgb, brgb, Wtir, btir,
                                          Wt1, bt1, Wt2, bt2, out);
}

// round 2
// speedup vs baseline: 1.1339x; 1.1339x over previous
#include <cuda_runtime.h>
#include <math.h>

#define E_EXPERTS 5
#define CDIM      256
#define HALF      128
#define QUART     64
#define BDIM      8
#define NPIX      6400
#define PIX       32

typedef unsigned long long u64;

__device__ int   g_expert[BDIM];
__device__ float g_pooled[BDIM * CDIM];

// ---------- packed f32x2 helpers ----------
__device__ __forceinline__ u64 pack2(float a, float b) {
    u64 r; asm("mov.b64 %0,{%1,%2};" : "=l"(r) : "f"(a), "f"(b)); return r;
}
__device__ __forceinline__ float2 unpack2(u64 v) {
    float2 f; asm("mov.b64 {%0,%1},%2;" : "=f"(f.x), "=f"(f.y) : "l"(v)); return f;
}
__device__ __forceinline__ u64 fma2(u64 a, u64 b, u64 c) {
    u64 d; asm("fma.rn.f32x2 %0,%1,%2,%3;" : "=l"(d) : "l"(a), "l"(b), "l"(c)); return d;
}
__device__ __forceinline__ u64 add2(u64 a, u64 b) {
    u64 d; asm("add.rn.f32x2 %0,%1,%2;" : "=l"(d) : "l"(a), "l"(b)); return d;
}

// ---------- gate kernel 1: pooled[b][c] = mean over 6400 pixels ----------
__global__ void __launch_bounds__(256) gate_pool(const float* __restrict__ x) {
    int bc = blockIdx.x;                       // b*256 + c
    const float4* p4 = (const float4*)(x + (size_t)bc * NPIX);
    float s = 0.f;
    for (int i = threadIdx.x; i < NPIX / 4; i += 256) {
        float4 v = __ldg(p4 + i);
        s += (v.x + v.y) + (v.z + v.w);
    }
    __shared__ float red[32];
    #pragma unroll
    for (int o = 16; o; o >>= 1) s += __shfl_down_sync(0xffffffffu, s, o);
    if ((threadIdx.x & 31) == 0) red[threadIdx.x >> 5] = s;
    __syncthreads();
    if (threadIdx.x < 32) {
        float v = (threadIdx.x < 8) ? red[threadIdx.x] : 0.f;
        #pragma unroll
        for (int o = 4; o; o >>= 1) v += __shfl_down_sync(0xffffffffu, v, o);
        if (threadIdx.x == 0) g_pooled[bc] = v * (1.0f / (float)NPIX);
    }
}

// ---------- gate kernel 2: argmax expert per batch ----------
__global__ void __launch_bounds__(256) gate_select(const float* __restrict__ Wg,
                                                   const float* __restrict__ bg) {
    int w = threadIdx.x >> 5, lane = threadIdx.x & 31;
    if (w >= BDIM) return;
    float best = -1e30f; int bi = 0;
    for (int e = 0; e < E_EXPERTS; e++) {
        float s = 0.f;
        for (int c = lane; c < CDIM; c += 32) s += g_pooled[w * CDIM + c] * Wg[e * CDIM + c];
        #pragma unroll
        for (int o = 16; o; o >>= 1) s += __shfl_down_sync(0xffffffffu, s, o);
        s += bg[e];
        s = __shfl_sync(0xffffffffu, s, 0);
        if (s > best) { best = s; bi = e; }   // strict > keeps first max
    }
    if (lane == 0) g_expert[w] = bi;
}

// ---------- smem layout (floats) ----------
// sWr : 128*128 = 16384   ([c*128 + o])
// sWt : 128*128 = 16384
// sW1 : 128*65  =  8320   ([o*65 + m])
// sX  : 256*34  =  8704   (rows padded to 34; reused as sH[2*2080] + sA[64])
// sD  : 2*16*129 u64 = 8256 floats  ([br*2064 + pair*129 + o] u64)
// total = 58048 floats = 232192 bytes  (max 232448)
#define SWR_OFF 0
#define SWT_OFF 16384
#define SW1_OFF 32768
#define SX_OFF  41088
#define SD_OFF  49792
#define SMEM_BYTES (58048 * 4)

__global__ void __launch_bounds__(256, 1) moe_expert(
    const float* __restrict__ x,
    const float* __restrict__ Wrgb, const float* __restrict__ brgb,
    const float* __restrict__ Wtir, const float* __restrict__ btir,
    const float* __restrict__ Wt1,  const float* __restrict__ bt1,
    const float* __restrict__ Wt2,  const float* __restrict__ bt2,
    float* __restrict__ out)
{
    extern __shared__ float sm[];
    float* sWr = sm + SWR_OFF;
    float* sWt = sm + SWT_OFF;
    float* sW1 = sm + SW1_OFF;
    float* sX  = sm + SX_OFF;
    float* sH  = sX;                  // [br*2080 + pix*65 + m]
    float* sA  = sX + 4160;           // [br*32 + pix]
    u64*   sD  = (u64*)(sm + SD_OFF); // [br*2064 + pair*129 + o]

    const int t  = threadIdx.x;
    const int br = t >> 7;            // branch: 0=RGB, 1=TIR
    const int og = (t >> 2) & 31;     // o = og + 32*i
    const int pg = t & 3;             // pair = pg*4 + j

    const int b = blockIdx.y;
    const int e = g_expert[b];

    const int ib    = blockIdx.x;     // 37 blocks/batch: 15x6 + 22x5 tiles
    const int tile0 = ib < 15 ? ib * 6 : 90 + (ib - 15) * 5;
    const int tcnt  = ib < 15 ? 6 : 5;

    // ---------------- prologue: stage weights once per block ----------------
    {
        const float* gWr = Wrgb + (size_t)e * HALF * HALF;
        const float* gWt = Wtir + (size_t)e * HALF * HALF;
        const int oo = t & 127, th = t >> 7;
        #pragma unroll 4
        for (int k = 0; k < 64; k++) {
            int c = k * 2 + th;
            sWr[c * 128 + oo] = __ldg(gWr + oo * 128 + c);
            sWt[c * 128 + oo] = __ldg(gWt + oo * 128 + c);
        }
        const float* gW1 = Wt1 + (size_t)e * QUART * HALF;
        #pragma unroll 4
        for (int k = 0; k < 32; k++) {
            int m = k * 2 + th;
            sW1[oo * 65 + m] = __ldg(gW1 + m * 128 + oo);
        }
    }

    for (int tt = 0; tt < tcnt; tt++) {
        const int pix0 = (tile0 + tt) * PIX;
        __syncthreads();   // protects sX/sD/sH/sA reuse (and prologue on first iter)

        // ---- x tile: 256 rows x 32 px into padded smem (rows of 34 floats) ----
        {
            const float* gX = x + (size_t)b * CDIM * NPIX + pix0;
            #pragma unroll
            for (int k = 0; k < 8; k++) {
                int lin = k * 256 + t;
                int c = lin >> 3, j = lin & 7;
                float4 v = __ldg((const float4*)(gX + (size_t)c * NPIX) + j);
                float* dst = sX + c * 34 + j * 4;
                *(float2*)(dst)     = make_float2(v.x, v.y);
                *(float2*)(dst + 2) = make_float2(v.z, v.w);
            }
        }
        __syncthreads();

        // ---- GEMM1: D = x + W@x + b, 4 o-channels x 4 pixel-pairs per thread ----
        {
            const float* wp = (br ? sWt : sWr) + og;
            const u64*   xp = (const u64*)sX + (size_t)br * 128 * 17 + pg * 4;
            u64 acc[4][4];
            #pragma unroll
            for (int i = 0; i < 4; i++)
                #pragma unroll
                for (int j = 0; j < 4; j++) acc[i][j] = 0ull;

            #pragma unroll 4
            for (int c = 0; c < 128; c++) {
                float w0s = wp[0], w1s = wp[32], w2s = wp[64], w3s = wp[96];
                u64 w0 = pack2(w0s, w0s), w1 = pack2(w1s, w1s);
                u64 w2 = pack2(w2s, w2s), w3 = pack2(w3s, w3s);
                u64 x0 = xp[0], x1 = xp[1], x2 = xp[2], x3 = xp[3];
                acc[0][0] = fma2(x0, w0, acc[0][0]);
                acc[0][1] = fma2(x1, w0, acc[0][1]);
                acc[0][2] = fma2(x2, w0, acc[0][2]);
                acc[0][3] = fma2(x3, w0, acc[0][3]);
                acc[1][0] = fma2(x0, w1, acc[1][0]);
                acc[1][1] = fma2(x1, w1, acc[1][1]);
                acc[1][2] = fma2(x2, w1, acc[1][2]);
                acc[1][3] = fma2(x3, w1, acc[1][3]);
                acc[2][0] = fma2(x0, w2, acc[2][0]);
                acc[2][1] = fma2(x1, w2, acc[2][1]);
                acc[2][2] = fma2(x2, w2, acc[2][2]);
                acc[2][3] = fma2(x3, w2, acc[2][3]);
                acc[3][0] = fma2(x0, w3, acc[3][0]);
                acc[3][1] = fma2(x1, w3, acc[3][1]);
                acc[3][2] = fma2(x2, w3, acc[3][2]);
                acc[3][3] = fma2(x3, w3, acc[3][3]);
                wp += 128; xp += 17;
            }

            // epilogue: + residual + bias -> sD
            const float* bp = (br ? btir : brgb) + e * HALF + og;
            const u64*   xb = (const u64*)sX + (size_t)br * 128 * 17 + pg * 4;
            u64* sDb = sD + br * 2064;
            #pragma unroll
            for (int i = 0; i < 4; i++) {
                float bv = __ldg(bp + 32 * i);
                u64 b2 = pack2(bv, bv);
                const u64* rr = xb + (og + 32 * i) * 17;
                #pragma unroll
                for (int j = 0; j < 4; j++) {
                    u64 dv = add2(add2(acc[i][j], rr[j]), b2);
                    sDb[(pg * 4 + j) * 129 + og + 32 * i] = dv;
                }
            }
        }
        __syncthreads();

        // ---- GEMM2: h[m][pix] = relu(Wt1 @ D + bt1), 2 m x 4 pairs per thread ----
        {
            const int mg = (t >> 2) & 31;              // m = mg*2 + i
            const float* w1p = sW1 + mg * 2;
            const u64*   dp  = sD + (size_t)br * 2064 + pg * 4 * 129;
            u64 h0[4], h1[4];
            #pragma unroll
            for (int j = 0; j < 4; j++) { h0[j] = 0ull; h1[j] = 0ull; }

            #pragma unroll 4
            for (int o2 = 0; o2 < 128; o2++) {
                float wa = w1p[0], wb = w1p[1];
                u64 w0 = pack2(wa, wa), w1v = pack2(wb, wb);
                u64 d0 = dp[0], d1 = dp[129], d2 = dp[258], d3 = dp[387];
                h0[0] = fma2(d0, w0, h0[0]);
                h0[1] = fma2(d1, w0, h0[1]);
                h0[2] = fma2(d2, w0, h0[2]);
                h0[3] = fma2(d3, w0, h0[3]);
                h1[0] = fma2(d0, w1v, h1[0]);
                h1[1] = fma2(d1, w1v, h1[1]);
                h1[2] = fma2(d2, w1v, h1[2]);
                h1[3] = fma2(d3, w1v, h1[3]);
                w1p += 65; dp += 1;
            }
            float bm0 = __ldg(bt1 + e * QUART + mg * 2);
            float bm1 = __ldg(bt1 + e * QUART + mg * 2 + 1);
            float* sHb = sH + br * 2080;
            #pragma unroll
            for (int j = 0; j < 4; j++) {
                int pix = (pg * 4 + j) * 2;
                float2 f0 = unpack2(h0[j]);
                float2 f1 = unpack2(h1[j]);
                sHb[pix * 65 + mg * 2]           = fmaxf(f0.x + bm0, 0.f);
                sHb[(pix + 1) * 65 + mg * 2]     = fmaxf(f0.y + bm0, 0.f);
                sHb[pix * 65 + mg * 2 + 1]       = fmaxf(f1.x + bm1, 0.f);
                sHb[(pix + 1) * 65 + mg * 2 + 1] = fmaxf(f1.y + bm1, 0.f);
            }
        }
        __syncthreads();

        // ---- attention scalars: a[br][pix] = sigmoid(Wt2 . h + bt2) ----
        if (t < 64) {
            int brr = t >> 5, p = t & 31;
            const float* hh = sH + brr * 2080 + p * 65;
            const float* w2 = Wt2 + e * QUART;
            float s0 = 0.f, s1 = 0.f, s2 = 0.f, s3 = 0.f;
            #pragma unroll
            for (int m = 0; m < 64; m += 4) {
                s0 += hh[m]     * __ldg(w2 + m);
                s1 += hh[m + 1] * __ldg(w2 + m + 1);
                s2 += hh[m + 2] * __ldg(w2 + m + 2);
                s3 += hh[m + 3] * __ldg(w2 + m + 3);
            }
            float sv = (s0 + s1) + (s2 + s3) + __ldg(bt2 + e);
            sA[brr * 32 + p] = 1.f / (1.f + expf(-sv));
        }
        __syncthreads();

        // ---- fused output: each thread 4 o x 4 consecutive pixels ----
        {
            int pr0 = (br * 4 + pg) * 2;          // first of 2 pairs
            int p0  = pr0 * 2;                    // first of 4 pixels
            float aR0 = sA[p0], aR1 = sA[p0 + 1], aR2 = sA[p0 + 2], aR3 = sA[p0 + 3];
            float aT0 = sA[32 + p0], aT1 = sA[32 + p0 + 1];
            float aT2 = sA[32 + p0 + 2], aT3 = sA[32 + p0 + 3];
            const u64* dR = sD + pr0 * 129;
            const u64* dT = sD + 2064 + pr0 * 129;
            float* go = out + ((size_t)(b * HALF + og)) * NPIX + pix0 + p0;
            #pragma unroll
            for (int i = 0; i < 4; i++) {
                int o = og + 32 * i;
                float2 r0 = unpack2(dR[o]), r1 = unpack2(dR[129 + o]);
                float2 t0 = unpack2(dT[o]), t1 = unpack2(dT[129 + o]);
                float4 v;
                v.x = aR0 * r0.x + aT0 * t0.x;
                v.y = aR1 * r0.y + aT1 * t0.y;
                v.z = aR2 * r1.x + aT2 * t1.x;
                v.w = aR3 * r1.y + aT3 * t1.y;
                *(float4*)(go + (size_t)32 * i * NPIX) = v;
            }
        }
    }
}

extern "C" void kernel_launch(void* const* d_in, const int* in_sizes, int n_in,
                              void* d_out, int out_size) {
    const float* x    = (const float*)d_in[0];
    const float* Wg   = (const float*)d_in[1];
    const float* bg   = (const float*)d_in[2];
    const float* Wrgb = (const float*)d_in[3];
    const float* brgb = (const float*)d_in[4];
    const float* Wtir = (const float*)d_in[5];
    const float* btir = (const float*)d_in[6];
    const float* Wt1  = (const float*)d_in[7];
    const float* bt1  = (const float*)d_in[8];
    const float* Wt2  = (const float*)d_in[9];
    const float* bt2  = (const float*)d_in[10];
    float* out = (float*)d_out;

    gate_pool<<<BDIM * CDIM, 256>>>(x);
    gate_select<<<1, 256>>>(Wg, bg);

    cudaFuncSetAttribute(moe_expert, cudaFuncAttributeMaxDynamicSharedMemorySize, SMEM_BYTES);
    dim3 grid(37, BDIM);
    moe_expert<<<grid, 256, SMEM_BYTES>>>(x, Wrgb, brgb, Wtir, btir,
                                          Wt1, bt1, Wt2, bt2, out);
}

// round 4
// speedup vs baseline: 2.1436x; 1.8905x over previous
#include <cuda_runtime.h>
#include <cstdint>
#include <math.h>

#define E_EXPERTS 5
#define CDIM      256
#define HALF      128
#define QUART     64
#define BDIM      8
#define NPIX      6400
#define PIX       32

typedef uint32_t u32;
typedef uint16_t u16;

__device__ int   g_expert[BDIM];
__device__ float g_pooled[BDIM * CDIM];

// ---------- bf16 helpers ----------
__device__ __forceinline__ float rtne_bf16(float f) {
    float r;
    asm("{\n .reg .b16 h;\n cvt.rn.bf16.f32 h, %1;\n cvt.f32.bf16 %0, h;\n}" : "=f"(r) : "f"(f));
    return r;
}
__device__ __forceinline__ u32 pack_bf16x2(float lo, float hi) {
    u32 r; asm("cvt.rn.bf16x2.f32 %0, %1, %2;" : "=r"(r) : "f"(hi), "f"(lo)); return r;
}
__device__ __forceinline__ u16 to_bf16(float f) {
    u16 h; asm("cvt.rn.bf16.f32 %0, %1;" : "=h"(h) : "f"(f)); return h;
}
__device__ __forceinline__ float from_bf16(u16 h) {
    float f; asm("cvt.f32.bf16 %0, %1;" : "=f"(f) : "h"(h)); return f;
}

// ---------- warp mma: D(16x8,f32) += A(16x16,bf16) * B(16x8,bf16) ----------
__device__ __forceinline__ void mma_bf16(float* d, const u32* a, const u32* b) {
    asm volatile("mma.sync.aligned.m16n8k16.row.col.f32.bf16.bf16.f32 "
        "{%0,%1,%2,%3},{%4,%5,%6,%7},{%8,%9},{%0,%1,%2,%3};"
        : "+f"(d[0]), "+f"(d[1]), "+f"(d[2]), "+f"(d[3])
        : "r"(a[0]), "r"(a[1]), "r"(a[2]), "r"(a[3]), "r"(b[0]), "r"(b[1]));
}

// ======================= gate kernels =======================
__global__ void __launch_bounds__(256) gate_pool(const float* __restrict__ x) {
    int bc = blockIdx.x;
    const float4* p4 = (const float4*)(x + (size_t)bc * NPIX);
    float s = 0.f;
    for (int i = threadIdx.x; i < NPIX / 4; i += 256) {
        float4 v = __ldg(p4 + i);
        s += (v.x + v.y) + (v.z + v.w);
    }
    __shared__ float red[32];
    #pragma unroll
    for (int o = 16; o; o >>= 1) s += __shfl_down_sync(0xffffffffu, s, o);
    if ((threadIdx.x & 31) == 0) red[threadIdx.x >> 5] = s;
    __syncthreads();
    if (threadIdx.x < 32) {
        float v = (threadIdx.x < 8) ? red[threadIdx.x] : 0.f;
        #pragma unroll
        for (int o = 4; o; o >>= 1) v += __shfl_down_sync(0xffffffffu, v, o);
        if (threadIdx.x == 0) g_pooled[bc] = v * (1.0f / (float)NPIX);
    }
}

__global__ void __launch_bounds__(256) gate_select(const float* __restrict__ Wg,
                                                   const float* __restrict__ bg) {
    int w = threadIdx.x >> 5, lane = threadIdx.x & 31;
    if (w >= BDIM) return;
    float best = -1e30f; int bi = 0;
    for (int e = 0; e < E_EXPERTS; e++) {
        float s = 0.f;
        for (int c = lane; c < CDIM; c += 32) s += g_pooled[w * CDIM + c] * Wg[e * CDIM + c];
        #pragma unroll
        for (int o = 16; o; o >>= 1) s += __shfl_down_sync(0xffffffffu, s, o);
        s += bg[e];
        s = __shfl_sync(0xffffffffu, s, 0);
        if (s > best) { best = s; bi = e; }
    }
    if (lane == 0) g_expert[w] = bi;
}

// ======================= smem layout (bytes) =======================
// All bf16 matrices use split-row layout: K=128 split into 2 planes of 64
// elems; each row = 64 bf16 (128B) padded to 144B (36 words, 36 mod 32 = 4
// -> fragment LDS at row*144 + q*4 hits banks 4*gr+q: conflict-free).
//
// Region A (36864 B), time-multiplexed per tile:
//   phase 1: Bx(br,hl) = (br*2+hl)*9216, each = 2 planes x 32rows x 144B
//   phase 2: D (same addressing, written after GEMM1)
//   phase 3: sH fp32 [br*2080+px*65+m] (16640 B) + sDt fp32 [o*33+px] @16640 (16896 B)
// W   (147456 B): buf(br,hl) = W_OFF + (br*2+hl)*36864, 2 planes x 128r x 144B
// W1  (36864 B):  buf(hl)    = W1_OFF + hl*18432,       2 planes x 64r x 144B
// sA  (256 B)
#define REGA_OFF 0
#define W_OFF    36864
#define W1_OFF   184320
#define SA_OFF   221184
#define SMEM_BYTES 221440

__global__ void __launch_bounds__(256, 1) moe_expert(
    const float* __restrict__ x,
    const float* __restrict__ Wrgb, const float* __restrict__ brgb,
    const float* __restrict__ Wtir, const float* __restrict__ btir,
    const float* __restrict__ Wt1,  const float* __restrict__ bt1,
    const float* __restrict__ Wt2,  const float* __restrict__ bt2,
    float* __restrict__ out)
{
    extern __shared__ char smc[];
    float* sA = (float*)(smc + SA_OFF);

    const int t    = threadIdx.x;
    const int w    = t >> 5;
    const int lane = t & 31;
    const int gr   = lane >> 2;     // fragment group row
    const int q    = lane & 3;      // thread-in-group
    const int br   = w >> 2;        // branch: 0=RGB, 1=TIR
    const int ms   = w & 3;         // m-slice within branch

    const int b = blockIdx.y;
    const int e = g_expert[b];

    const int ib    = blockIdx.x;
    const int tile0 = ib < 15 ? ib * 6 : 90 + (ib - 15) * 5;
    const int tcnt  = ib < 15 ? 6 : 5;

    // ---------------- prologue: W, W1 -> bf16 hi/lo in smem ----------------
    #pragma unroll
    for (int br2 = 0; br2 < 2; br2++) {
        const float* gW = (br2 ? Wtir : Wrgb) + (size_t)e * HALF * HALF;
        char* bh = smc + W_OFF + (br2 * 2) * 36864;
        char* bl = bh + 36864;
        #pragma unroll 4
        for (int it = 0; it < 32; it++) {
            int lin = it * 256 + t;            // 8192 = 128 o x 64 c-pairs
            int o = lin >> 6, c0 = (lin & 63) * 2;
            float2 v = __ldg((const float2*)(gW + o * 128 + c0));
            float h0 = rtne_bf16(v.x), h1 = rtne_bf16(v.y);
            int addr = (c0 >> 6) * 18432 + o * 144 + (c0 & 63) * 2;
            *(u32*)(bh + addr) = pack_bf16x2(h0, h1);
            *(u32*)(bl + addr) = pack_bf16x2(v.x - h0, v.y - h1);
        }
    }
    {
        const float* g1 = Wt1 + (size_t)e * QUART * HALF;
        char* bh = smc + W1_OFF;
        char* bl = bh + 18432;
        #pragma unroll 4
        for (int it = 0; it < 16; it++) {
            int lin = it * 256 + t;            // 4096 = 64 m x 64 c-pairs
            int m = lin >> 6, c0 = (lin & 63) * 2;
            float2 v = __ldg((const float2*)(g1 + m * 128 + c0));
            float h0 = rtne_bf16(v.x), h1 = rtne_bf16(v.y);
            int addr = (c0 >> 6) * 9216 + m * 144 + (c0 & 63) * 2;
            *(u32*)(bh + addr) = pack_bf16x2(h0, h1);
            *(u32*)(bl + addr) = pack_bf16x2(v.x - h0, v.y - h1);
        }
    }

    for (int tt = 0; tt < tcnt; tt++) {
        const int pix0 = (tile0 + tt) * PIX;
        __syncthreads();   // region A handoff (prev tile's sH/sDt done; prologue on it 0)

        // ---- build x bf16 hi/lo B-tiles straight from gmem ----
        {
            int c0  = 2 * (t & 127);           // channel pair (0..254)
            int pxh = t >> 7;                  // px half: 16 px
            int br2 = c0 >> 7, ci = c0 & 127;
            const float* g0 = x + ((size_t)(b * CDIM + c0)) * NPIX + pix0 + pxh * 16;
            float4 r0[4], r1[4];
            #pragma unroll
            for (int j = 0; j < 4; j++) {
                r0[j] = __ldg((const float4*)g0 + j);
                r1[j] = __ldg((const float4*)(g0 + NPIX) + j);
            }
            char* bh = smc + (br2 * 2) * 9216 + ((ci & 64) ? 4608 : 0);
            char* bl = bh + 9216;
            const int inner2 = (ci & 63) * 2;
            const float* f0 = (const float*)r0;
            const float* f1 = (const float*)r1;
            #pragma unroll
            for (int j = 0; j < 16; j++) {
                int px = pxh * 16 + j;
                float a0v = f0[j], a1v = f1[j];
                float h0 = rtne_bf16(a0v), h1 = rtne_bf16(a1v);
                int addr = px * 144 + inner2;
                *(u32*)(bh + addr) = pack_bf16x2(h0, h1);
                *(u32*)(bl + addr) = pack_bf16x2(a0v - h0, a1v - h1);
            }
        }
        __syncthreads();

        // ---- GEMM1: acc[2][4] frags = Whi@xhi + Whi@xlo + Wlo@xhi ----
        float acc[2][4][4];
        #pragma unroll
        for (int mt = 0; mt < 2; mt++)
            #pragma unroll
            for (int nt = 0; nt < 4; nt++)
                #pragma unroll
                for (int i = 0; i < 4; i++) acc[mt][nt][i] = 0.f;

        const int rbase = ms * 32;
        {
            const char* Ah = smc + W_OFF + (br * 2) * 36864;
            const char* Al = Ah + 36864;
            const char* Bh = smc + (br * 2) * 9216;
            const char* Bl = Bh + 9216;
            #pragma unroll 4
            for (int kt = 0; kt < 8; kt++) {
                const int wp = (kt >> 2) * 18432 + (kt & 3) * 32 + q * 4;
                const int bp = (kt >> 2) * 4608  + (kt & 3) * 32 + q * 4;
                u32 ah[2][4], al[2][4], bh[4][2], bl[4][2];
                #pragma unroll
                for (int mt = 0; mt < 2; mt++) {
                    int rb  = (rbase + mt * 16 + gr) * 144;
                    int rb8 = rb + 8 * 144;
                    ah[mt][0] = *(const u32*)(Ah + wp + rb);
                    ah[mt][1] = *(const u32*)(Ah + wp + rb8);
                    ah[mt][2] = *(const u32*)(Ah + wp + rb + 16);
                    ah[mt][3] = *(const u32*)(Ah + wp + rb8 + 16);
                    al[mt][0] = *(const u32*)(Al + wp + rb);
                    al[mt][1] = *(const u32*)(Al + wp + rb8);
                    al[mt][2] = *(const u32*)(Al + wp + rb + 16);
                    al[mt][3] = *(const u32*)(Al + wp + rb8 + 16);
                }
                #pragma unroll
                for (int nt = 0; nt < 4; nt++) {
                    int nb = (nt * 8 + gr) * 144;
                    bh[nt][0] = *(const u32*)(Bh + bp + nb);
                    bh[nt][1] = *(const u32*)(Bh + bp + nb + 16);
                    bl[nt][0] = *(const u32*)(Bl + bp + nb);
                    bl[nt][1] = *(const u32*)(Bl + bp + nb + 16);
                }
                #pragma unroll
                for (int mt = 0; mt < 2; mt++)
                    #pragma unroll
                    for (int nt = 0; nt < 4; nt++) {
                        mma_bf16(acc[mt][nt], ah[mt], bh[nt]);
                        mma_bf16(acc[mt][nt], ah[mt], bl[nt]);
                        mma_bf16(acc[mt][nt], al[mt], bh[nt]);
                    }
            }
        }

        // ---- GEMM1 epilogue: + residual + bias (exact fp32, kept in acc) ----
        {
            const float* biasp = (br ? btir : brgb) + e * HALF;
            const float* gxr = x + ((size_t)(b * CDIM) + br * HALF) * NPIX + pix0;
            #pragma unroll
            for (int mt = 0; mt < 2; mt++) {
                int rr0 = rbase + mt * 16 + gr, rr1 = rr0 + 8;
                float bz0 = __ldg(biasp + rr0), bz1 = __ldg(biasp + rr1);
                #pragma unroll
                for (int nt = 0; nt < 4; nt++) {
                    int c0 = nt * 8 + 2 * q;
                    float2 x0 = __ldg((const float2*)(gxr + (size_t)rr0 * NPIX + c0));
                    float2 x1 = __ldg((const float2*)(gxr + (size_t)rr1 * NPIX + c0));
                    acc[mt][nt][0] += x0.x + bz0;
                    acc[mt][nt][1] += x0.y + bz0;
                    acc[mt][nt][2] += x1.x + bz1;
                    acc[mt][nt][3] += x1.y + bz1;
                }
            }
        }
        __syncthreads();   // all Bx reads done before overwriting with D

        // ---- store D as bf16 hi/lo B-tiles (overwrites Bx region) ----
        {
            char* Dh = smc + (br * 2) * 9216;
            char* Dl = Dh + 9216;
            #pragma unroll
            for (int mt = 0; mt < 2; mt++) {
                int rr0 = rbase + mt * 16 + gr, rr1 = rr0 + 8;
                #pragma unroll
                for (int nt = 0; nt < 4; nt++) {
                    int c0 = nt * 8 + 2 * q;
                    #pragma unroll
                    for (int i = 0; i < 4; i++) {
                        int r = (i < 2) ? rr0 : rr1;
                        int c = c0 + (i & 1);
                        float v = acc[mt][nt][i];
                        u16 hb = to_bf16(v);
                        u16 lb = to_bf16(v - from_bf16(hb));
                        int addr = ((r & 64) ? 4608 : 0) + c * 144 + (r & 63) * 2;
                        *(u16*)(Dh + addr) = hb;
                        *(u16*)(Dl + addr) = lb;
                    }
                }
            }
        }
        __syncthreads();

        // ---- GEMM2: h frags = W1hi@Dhi + W1hi@Dlo + W1lo@Dhi ----
        float acc2[4][4];
        #pragma unroll
        for (int nt = 0; nt < 4; nt++)
            #pragma unroll
            for (int i = 0; i < 4; i++) acc2[nt][i] = 0.f;
        {
            const char* Ah = smc + W1_OFF;
            const char* Al = Ah + 18432;
            const char* Bh = smc + (br * 2) * 9216;
            const char* Bl = Bh + 9216;
            const int mrow = ms * 16 + gr;
            #pragma unroll 4
            for (int kt = 0; kt < 8; kt++) {
                const int wp = (kt >> 2) * 9216 + (kt & 3) * 32 + q * 4;
                const int bp = (kt >> 2) * 4608 + (kt & 3) * 32 + q * 4;
                int rb = mrow * 144, rb8 = rb + 8 * 144;
                u32 ah[4], al[4], bh[4][2], bl[4][2];
                ah[0] = *(const u32*)(Ah + wp + rb);
                ah[1] = *(const u32*)(Ah + wp + rb8);
                ah[2] = *(const u32*)(Ah + wp + rb + 16);
                ah[3] = *(const u32*)(Ah + wp + rb8 + 16);
                al[0] = *(const u32*)(Al + wp + rb);
                al[1] = *(const u32*)(Al + wp + rb8);
                al[2] = *(const u32*)(Al + wp + rb + 16);
                al[3] = *(const u32*)(Al + wp + rb8 + 16);
                #pragma unroll
                for (int nt = 0; nt < 4; nt++) {
                    int nb = (nt * 8 + gr) * 144;
                    bh[nt][0] = *(const u32*)(Bh + bp + nb);
                    bh[nt][1] = *(const u32*)(Bh + bp + nb + 16);
                    bl[nt][0] = *(const u32*)(Bl + bp + nb);
                    bl[nt][1] = *(const u32*)(Bl + bp + nb + 16);
                }
                #pragma unroll
                for (int nt = 0; nt < 4; nt++) {
                    mma_bf16(acc2[nt], ah, bh[nt]);
                    mma_bf16(acc2[nt], ah, bl[nt]);
                    mma_bf16(acc2[nt], al, bh[nt]);
                }
            }
        }
        __syncthreads();   // D reads done before overwriting region A with sH/sDt

        // ---- h epilogue: relu(h + bt1) -> sH fp32 ----
        {
            float* sH = (float*)smc;           // [br*2080 + px*65 + m]
            const int mrow = ms * 16 + gr;
            float bz0 = __ldg(bt1 + e * QUART + mrow);
            float bz1 = __ldg(bt1 + e * QUART + mrow + 8);
            float* sHb = sH + br * 2080;
            #pragma unroll
            for (int nt = 0; nt < 4; nt++) {
                int c0 = nt * 8 + 2 * q;
                sHb[c0 * 65 + mrow]           = fmaxf(acc2[nt][0] + bz0, 0.f);
                sHb[(c0 + 1) * 65 + mrow]     = fmaxf(acc2[nt][1] + bz0, 0.f);
                sHb[c0 * 65 + mrow + 8]       = fmaxf(acc2[nt][2] + bz1, 0.f);
                sHb[(c0 + 1) * 65 + mrow + 8] = fmaxf(acc2[nt][3] + bz1, 0.f);
            }
        }
        __syncthreads();

        // ---- attention (warps 0-1) + TIR stages raw D (warps 4-7) ----
        {
            float* sH  = (float*)smc;
            float* sDt = (float*)(smc + 16640);    // [o*33 + px] fp32
            if (t < 64) {
                int brr = t >> 5, p = t & 31;
                const float* hh = sH + brr * 2080 + p * 65;
                const float* w2 = Wt2 + e * QUART;
                float s0 = 0.f, s1 = 0.f, s2 = 0.f, s3 = 0.f;
                #pragma unroll
                for (int m = 0; m < 64; m += 4) {
                    s0 += hh[m]     * __ldg(w2 + m);
                    s1 += hh[m + 1] * __ldg(w2 + m + 1);
                    s2 += hh[m + 2] * __ldg(w2 + m + 2);
                    s3 += hh[m + 3] * __ldg(w2 + m + 3);
                }
                float sv = (s0 + s1) + (s2 + s3) + __ldg(bt2 + e);
                sA[brr * 32 + p] = 1.f / (1.f + expf(-sv));
            }
            if (br == 1) {
                #pragma unroll
                for (int mt = 0; mt < 2; mt++) {
                    int rr0 = rbase + mt * 16 + gr, rr1 = rr0 + 8;
                    #pragma unroll
                    for (int nt = 0; nt < 4; nt++) {
                        int c0 = nt * 8 + 2 * q;
                        sDt[rr0 * 33 + c0]     = acc[mt][nt][0];
                        sDt[rr0 * 33 + c0 + 1] = acc[mt][nt][1];
                        sDt[rr1 * 33 + c0]     = acc[mt][nt][2];
                        sDt[rr1 * 33 + c0 + 1] = acc[mt][nt][3];
                    }
                }
            }
        }
        __syncthreads();

        // ---- fuse + store (RGB warps): out = aR*Dr + aT*Dt ----
        if (br == 0) {
            const float* sDt = (const float*)(smc + 16640);
            float* go = out + (size_t)(b * HALF) * NPIX + pix0;
            #pragma unroll
            for (int mt = 0; mt < 2; mt++) {
                int rr0 = rbase + mt * 16 + gr, rr1 = rr0 + 8;
                #pragma unroll
                for (int nt = 0; nt < 4; nt++) {
                    int c0 = nt * 8 + 2 * q;
                    float aR0 = sA[c0], aR1 = sA[c0 + 1];
                    float aT0 = sA[32 + c0], aT1 = sA[32 + c0 + 1];
                    float2 v0, v1;
                    v0.x = aR0 * acc[mt][nt][0] + aT0 * sDt[rr0 * 33 + c0];
                    v0.y = aR1 * acc[mt][nt][1] + aT1 * sDt[rr0 * 33 + c0 + 1];
                    v1.x = aR0 * acc[mt][nt][2] + aT0 * sDt[rr1 * 33 + c0];
                    v1.y = aR1 * acc[mt][nt][3] + aT1 * sDt[rr1 * 33 + c0 + 1];
                    *(float2*)(go + (size_t)rr0 * NPIX + c0) = v0;
                    *(float2*)(go + (size_t)rr1 * NPIX + c0) = v1;
                }
            }
        }
    }
}

extern "C" void kernel_launch(void* const* d_in, const int* in_sizes, int n_in,
                              void* d_out, int out_size) {
    const float* x    = (const float*)d_in[0];
    const float* Wg   = (const float*)d_in[1];
    const float* bg   = (const float*)d_in[2];
    const float* Wrgb = (const float*)d_in[3];
    const float* brgb = (const float*)d_in[4];
    const float* Wtir = (const float*)d_in[5];
    const float* btir = (const float*)d_in[6];
    const float* Wt1  = (const float*)d_in[7];
    const float* bt1  = (const float*)d_in[8];
    const float* Wt2  = (const float*)d_in[9];
    const float* bt2  = (const float*)d_in[10];
    float* out = (float*)d_out;

    gate_pool<<<BDIM * CDIM, 256>>>(x);
    gate_select<<<1, 256>>>(Wg, bg);

    cudaFuncSetAttribute(moe_expert, cudaFuncAttributeMaxDynamicSharedMemorySize, SMEM_BYTES);
    dim3 grid(37, BDIM);
    moe_expert<<<grid, 256, SMEM_BYTES>>>(x, Wrgb, brgb, Wtir, btir,
                                          Wt1, bt1, Wt2, bt2, out);
}

// round 5
// speedup vs baseline: 2.3037x; 1.0747x over previous
#include <cuda_runtime.h>
#include <cstdint>
#include <math.h>

#define E_EXPERTS 5
#define CDIM      256
#define HALF      128
#define QUART     64
#define BDIM      8
#define NPIX      6400
#define PIX       32

typedef uint32_t u32;
typedef uint16_t u16;

__device__ int   g_expert[BDIM];
__device__ float g_pooled[BDIM * CDIM];

// ---------- bf16 helpers ----------
__device__ __forceinline__ float rtne_bf16(float f) {
    float r;
    asm("{\n .reg .b16 h;\n cvt.rn.bf16.f32 h, %1;\n cvt.f32.bf16 %0, h;\n}" : "=f"(r) : "f"(f));
    return r;
}
__device__ __forceinline__ u32 pack_bf16x2(float lo, float hi) {
    u32 r; asm("cvt.rn.bf16x2.f32 %0, %1, %2;" : "=r"(r) : "f"(hi), "f"(lo)); return r;
}
__device__ __forceinline__ u16 to_bf16(float f) {
    u16 h; asm("cvt.rn.bf16.f32 %0, %1;" : "=h"(h) : "f"(f)); return h;
}
__device__ __forceinline__ float from_bf16(u16 h) {
    float f; asm("cvt.f32.bf16 %0, %1;" : "=f"(f) : "h"(h)); return f;
}

// ---------- warp mma: D(16x8,f32) += A(16x16,bf16row) * B(16x8,bf16col) ----------
__device__ __forceinline__ void mma_bf16(float* d, const u32* a, const u32* b) {
    asm volatile("mma.sync.aligned.m16n8k16.row.col.f32.bf16.bf16.f32 "
        "{%0,%1,%2,%3},{%4,%5,%6,%7},{%8,%9},{%0,%1,%2,%3};"
        : "+f"(d[0]), "+f"(d[1]), "+f"(d[2]), "+f"(d[3])
        : "r"(a[0]), "r"(a[1]), "r"(a[2]), "r"(a[3]), "r"(b[0]), "r"(b[1]));
}

// ======================= gate kernels =======================
__global__ void __launch_bounds__(256) gate_pool(const float* __restrict__ x) {
    int bc = blockIdx.x;
    const float4* p4 = (const float4*)(x + (size_t)bc * NPIX);
    float s = 0.f;
    for (int i = threadIdx.x; i < NPIX / 4; i += 256) {
        float4 v = __ldg(p4 + i);
        s += (v.x + v.y) + (v.z + v.w);
    }
    __shared__ float red[32];
    #pragma unroll
    for (int o = 16; o; o >>= 1) s += __shfl_down_sync(0xffffffffu, s, o);
    if ((threadIdx.x & 31) == 0) red[threadIdx.x >> 5] = s;
    __syncthreads();
    if (threadIdx.x < 32) {
        float v = (threadIdx.x < 8) ? red[threadIdx.x] : 0.f;
        #pragma unroll
        for (int o = 4; o; o >>= 1) v += __shfl_down_sync(0xffffffffu, v, o);
        if (threadIdx.x == 0) g_pooled[bc] = v * (1.0f / (float)NPIX);
    }
}

__global__ void __launch_bounds__(256) gate_select(const float* __restrict__ Wg,
                                                   const float* __restrict__ bg) {
    int w = threadIdx.x >> 5, lane = threadIdx.x & 31;
    if (w >= BDIM) return;
    float best = -1e30f; int bi = 0;
    for (int e = 0; e < E_EXPERTS; e++) {
        float s = 0.f;
        for (int c = lane; c < CDIM; c += 32) s += g_pooled[w * CDIM + c] * Wg[e * CDIM + c];
        #pragma unroll
        for (int o = 16; o; o >>= 1) s += __shfl_down_sync(0xffffffffu, s, o);
        s += bg[e];
        s = __shfl_sync(0xffffffffu, s, 0);
        if (s > best) { best = s; bi = e; }
    }
    if (lane == 0) g_expert[w] = bi;
}

// ======================= smem layout (bytes) =======================
// Split-row bf16 layout: K=128 in 2 planes of 64; row = 64 bf16 = 128B
// padded to 144B.
// Region A (36864B), time-multiplexed per tile:
//   phase 1: Bx(br,hl) = (br*2+hl)*9216 (2 planes x 32 px-rows x 144B)
//   phase 2: D (same addressing)
//   phase 3: sDt fp32 [o*33+px] (16896B)
// W  : W_OFF + (br*2+hl)*36864 (2 planes x 128 rows x 144B)
// W1 : W1_OFF + hl*18432       (2 planes x 64 rows x 144B)
// sA : 64 f32 @ SA_OFF;  sS : 64 f32 @ SS_OFF
#define W_OFF    36864
#define W1_OFF   184320
#define SA_OFF   221184
#define SS_OFF   221440
#define SMEM_BYTES 221696

__global__ void __launch_bounds__(512, 1) moe_expert(
    const float* __restrict__ x,
    const float* __restrict__ Wrgb, const float* __restrict__ brgb,
    const float* __restrict__ Wtir, const float* __restrict__ btir,
    const float* __restrict__ Wt1,  const float* __restrict__ bt1,
    const float* __restrict__ Wt2,  const float* __restrict__ bt2,
    float* __restrict__ out)
{
    extern __shared__ char smc[];
    float* sA = (float*)(smc + SA_OFF);
    float* sS = (float*)(smc + SS_OFF);

    const int t    = threadIdx.x;
    const int w    = t >> 5;
    const int lane = t & 31;
    const int gr   = lane >> 2;
    const int q    = lane & 3;
    const int br   = w >> 3;            // branch: 0=RGB, 1=TIR
    const int msub = w & 7;
    const int rbase = msub * 16;        // GEMM1 o-rows

    const int b = blockIdx.y;
    const int e = g_expert[b];

    const int ib    = blockIdx.x;
    const int tile0 = ib < 15 ? ib * 6 : 90 + (ib - 15) * 5;
    const int tcnt  = ib < 15 ? 6 : 5;

    // ---- hoisted per-thread constants ----
    const float bz0 = __ldg((br ? btir : brgb) + e * HALF + rbase + gr);
    const float bz1 = __ldg((br ? btir : brgb) + e * HALF + rbase + gr + 8);
    const int   pxt   = msub >> 2;      // GEMM2 px tile
    const int   npair = msub & 3;       // GEMM2 n8-pair
    float w2x[2], w2y[2], b1x[2], b1y[2];
    #pragma unroll
    for (int j = 0; j < 2; j++) {
        int m0 = (npair * 2 + j) * 8 + 2 * q;
        w2x[j] = __ldg(Wt2 + e * QUART + m0);
        w2y[j] = __ldg(Wt2 + e * QUART + m0 + 1);
        b1x[j] = __ldg(bt1 + e * QUART + m0);
        b1y[j] = __ldg(bt1 + e * QUART + m0 + 1);
    }
    const float bt2v = __ldg(bt2 + e);

    // ---------------- prologue: W, W1 -> bf16 hi/lo in smem ----------------
    #pragma unroll
    for (int br2 = 0; br2 < 2; br2++) {
        const float* gW = (br2 ? Wtir : Wrgb) + (size_t)e * HALF * HALF;
        char* bh = smc + W_OFF + (br2 * 2) * 36864;
        char* bl = bh + 36864;
        #pragma unroll 4
        for (int it = 0; it < 16; it++) {
            int lin = it * 512 + t;            // 8192 = 128 o x 64 c-pairs
            int o = lin >> 6, c0 = (lin & 63) * 2;
            float2 v = __ldg((const float2*)(gW + o * 128 + c0));
            float h0 = rtne_bf16(v.x), h1 = rtne_bf16(v.y);
            int addr = (c0 >> 6) * 18432 + o * 144 + (c0 & 63) * 2;
            *(u32*)(bh + addr) = pack_bf16x2(h0, h1);
            *(u32*)(bl + addr) = pack_bf16x2(v.x - h0, v.y - h1);
        }
    }
    {
        const float* g1 = Wt1 + (size_t)e * QUART * HALF;
        char* bh = smc + W1_OFF;
        char* bl = bh + 18432;
        #pragma unroll 4
        for (int it = 0; it < 8; it++) {
            int lin = it * 512 + t;            // 4096 = 64 m x 64 c-pairs
            int m = lin >> 6, c0 = (lin & 63) * 2;
            float2 v = __ldg((const float2*)(g1 + m * 128 + c0));
            float h0 = rtne_bf16(v.x), h1 = rtne_bf16(v.y);
            int addr = (c0 >> 6) * 9216 + m * 144 + (c0 & 63) * 2;
            *(u32*)(bh + addr) = pack_bf16x2(h0, h1);
            *(u32*)(bl + addr) = pack_bf16x2(v.x - h0, v.y - h1);
        }
    }

    // ---- x double-buffer setup: thread = (channel-pair, px-quarter) ----
    const int cp  = t & 127, c0x = 2 * cp, pxq = t >> 7;     // pxq 0..3
    const int brx = c0x >> 7;
    const int plx = (c0x & 64) ? 4608 : 0;
    const int cin = (c0x & 63) * 2;
    const float* gx0 = x + ((size_t)(b * CDIM + c0x)) * NPIX + pxq * 8;

    float xa[8], xb[8];
    {
        const float* g = gx0 + tile0 * PIX;
        *(float4*)xa       = __ldg((const float4*)g);
        *(float4*)(xa + 4) = __ldg((const float4*)(g + 4));
        *(float4*)xb       = __ldg((const float4*)(g + NPIX));
        *(float4*)(xb + 4) = __ldg((const float4*)(g + NPIX + 4));
    }

    for (int tt = 0; tt < tcnt; tt++) {
        const int pix0 = (tile0 + tt) * PIX;
        __syncthreads();   // region A free (prev tile done / prologue on tt=0)

        // ---- write Bx bf16 hi/lo from regs ----
        {
            char* bh = smc + (brx * 2) * 9216 + plx;
            char* bl = bh + 9216;
            #pragma unroll
            for (int j = 0; j < 8; j++) {
                int px = pxq * 8 + j;
                float h0 = rtne_bf16(xa[j]), h1 = rtne_bf16(xb[j]);
                int addr = px * 144 + cin;
                *(u32*)(bh + addr) = pack_bf16x2(h0, h1);
                *(u32*)(bl + addr) = pack_bf16x2(xa[j] - h0, xb[j] - h1);
            }
        }
        __syncthreads();

        // ---- prefetch next tile's x (hidden under GEMMs) ----
        float na[8], nb[8];
        const bool more = (tt + 1 < tcnt);
        if (more) {
            const float* g = gx0 + pix0 + PIX;
            *(float4*)na       = __ldg((const float4*)g);
            *(float4*)(na + 4) = __ldg((const float4*)(g + 4));
            *(float4*)nb       = __ldg((const float4*)(g + NPIX));
            *(float4*)(nb + 4) = __ldg((const float4*)(g + NPIX + 4));
        }

        // ---- GEMM1: acc[4][4] = Whi@xhi + Whi@xlo + Wlo@xhi ----
        float acc[4][4];
        #pragma unroll
        for (int nt = 0; nt < 4; nt++)
            #pragma unroll
            for (int i = 0; i < 4; i++) acc[nt][i] = 0.f;

        // residual prefetch (L2-hot)
        float2 rx0[4], rx1[4];
        {
            const float* gxr = x + ((size_t)(b * CDIM) + br * HALF) * NPIX + pix0;
            #pragma unroll
            for (int nt = 0; nt < 4; nt++) {
                int c0 = nt * 8 + 2 * q;
                rx0[nt] = __ldg((const float2*)(gxr + (size_t)(rbase + gr) * NPIX + c0));
                rx1[nt] = __ldg((const float2*)(gxr + (size_t)(rbase + gr + 8) * NPIX + c0));
            }
        }
        {
            const char* Ah = smc + W_OFF + (br * 2) * 36864;
            const char* Al = Ah + 36864;
            const char* Bh = smc + (br * 2) * 9216;
            const char* Bl = Bh + 9216;
            const int rb = (rbase + gr) * 144, rb8 = rb + 1152;
            #pragma unroll 4
            for (int kt = 0; kt < 8; kt++) {
                const int wp = (kt >> 2) * 18432 + (kt & 3) * 32 + q * 4;
                const int bp = (kt >> 2) * 4608  + (kt & 3) * 32 + q * 4;
                u32 ah[4], al[4], bh[4][2], bl[4][2];
                ah[0] = *(const u32*)(Ah + wp + rb);
                ah[1] = *(const u32*)(Ah + wp + rb8);
                ah[2] = *(const u32*)(Ah + wp + rb + 16);
                ah[3] = *(const u32*)(Ah + wp + rb8 + 16);
                al[0] = *(const u32*)(Al + wp + rb);
                al[1] = *(const u32*)(Al + wp + rb8);
                al[2] = *(const u32*)(Al + wp + rb + 16);
                al[3] = *(const u32*)(Al + wp + rb8 + 16);
                #pragma unroll
                for (int nt = 0; nt < 4; nt++) {
                    int nb2 = (nt * 8 + gr) * 144;
                    bh[nt][0] = *(const u32*)(Bh + bp + nb2);
                    bh[nt][1] = *(const u32*)(Bh + bp + nb2 + 16);
                    bl[nt][0] = *(const u32*)(Bl + bp + nb2);
                    bl[nt][1] = *(const u32*)(Bl + bp + nb2 + 16);
                }
                #pragma unroll
                for (int nt = 0; nt < 4; nt++) {
                    mma_bf16(acc[nt], ah, bh[nt]);
                    mma_bf16(acc[nt], ah, bl[nt]);
                    mma_bf16(acc[nt], al, bh[nt]);
                }
            }
        }
        // epilogue: + residual + bias (exact fp32, kept in acc)
        #pragma unroll
        for (int nt = 0; nt < 4; nt++) {
            acc[nt][0] += rx0[nt].x + bz0;
            acc[nt][1] += rx0[nt].y + bz0;
            acc[nt][2] += rx1[nt].x + bz1;
            acc[nt][3] += rx1[nt].y + bz1;
        }
        __syncthreads();   // Bx reads done

        // ---- store D bf16 hi/lo (overwrites Bx); zero sS ----
        {
            char* Dh = smc + (br * 2) * 9216;
            char* Dl = Dh + 9216;
            const int pl0 = (rbase & 64) ? 4608 : 0;
            const int in0 = ((rbase + gr) & 63) * 2;
            #pragma unroll
            for (int nt = 0; nt < 4; nt++) {
                int px0 = nt * 8 + 2 * q;
                #pragma unroll
                for (int i = 0; i < 4; i++) {
                    int px = px0 + (i & 1);
                    int in = in0 + ((i < 2) ? 0 : 16);
                    float v = acc[nt][i];
                    u16 hb = to_bf16(v);
                    u16 lb = to_bf16(v - from_bf16(hb));
                    int addr = pl0 + px * 144 + in;
                    *(u16*)(Dh + addr) = hb;
                    *(u16*)(Dl + addr) = lb;
                }
            }
            if (t < 64) sS[t] = 0.f;
        }
        __syncthreads();

        // ---- GEMM2': h^T = W1hi@Dhi + W1hi@Dlo + W1lo@Dhi; fused attention ----
        {
            float acc2[2][4];
            #pragma unroll
            for (int j = 0; j < 2; j++)
                #pragma unroll
                for (int i = 0; i < 4; i++) acc2[j][i] = 0.f;

            const char* A2h = smc + (br * 2) * 9216;   // D hi
            const char* A2l = A2h + 9216;              // D lo
            const char* B2h = smc + W1_OFF;            // W1 hi
            const char* B2l = B2h + 18432;             // W1 lo
            const int prb = (pxt * 16 + gr) * 144, prb8 = prb + 1152;
            #pragma unroll 4
            for (int kt = 0; kt < 8; kt++) {
                const int wpA = (kt >> 2) * 4608 + (kt & 3) * 32 + q * 4;
                const int wpB = (kt >> 2) * 9216 + (kt & 3) * 32 + q * 4;
                u32 ah[4], al[4], bh[2][2], bl[2][2];
                ah[0] = *(const u32*)(A2h + wpA + prb);
                ah[1] = *(const u32*)(A2h + wpA + prb8);
                ah[2] = *(const u32*)(A2h + wpA + prb + 16);
                ah[3] = *(const u32*)(A2h + wpA + prb8 + 16);
                al[0] = *(const u32*)(A2l + wpA + prb);
                al[1] = *(const u32*)(A2l + wpA + prb8);
                al[2] = *(const u32*)(A2l + wpA + prb + 16);
                al[3] = *(const u32*)(A2l + wpA + prb8 + 16);
                #pragma unroll
                for (int j = 0; j < 2; j++) {
                    int nb2 = ((npair * 2 + j) * 8 + gr) * 144;
                    bh[j][0] = *(const u32*)(B2h + wpB + nb2);
                    bh[j][1] = *(const u32*)(B2h + wpB + nb2 + 16);
                    bl[j][0] = *(const u32*)(B2l + wpB + nb2);
                    bl[j][1] = *(const u32*)(B2l + wpB + nb2 + 16);
                }
                #pragma unroll
                for (int j = 0; j < 2; j++) {
                    mma_bf16(acc2[j], ah, bh[j]);
                    mma_bf16(acc2[j], ah, bl[j]);
                    mma_bf16(acc2[j], al, bh[j]);
                }
            }
            // fused attention partials: s[px] += w2[m]*relu(h + bt1)
            float p0 = 0.f, p8 = 0.f;
            #pragma unroll
            for (int j = 0; j < 2; j++) {
                p0 += w2x[j] * fmaxf(acc2[j][0] + b1x[j], 0.f)
                    + w2y[j] * fmaxf(acc2[j][1] + b1y[j], 0.f);
                p8 += w2x[j] * fmaxf(acc2[j][2] + b1x[j], 0.f)
                    + w2y[j] * fmaxf(acc2[j][3] + b1y[j], 0.f);
            }
            p0 += __shfl_xor_sync(0xffffffffu, p0, 1);
            p0 += __shfl_xor_sync(0xffffffffu, p0, 2);
            p8 += __shfl_xor_sync(0xffffffffu, p8, 1);
            p8 += __shfl_xor_sync(0xffffffffu, p8, 2);
            if (q == 0) {
                atomicAdd(&sS[br * 32 + pxt * 16 + gr], p0);
                atomicAdd(&sS[br * 32 + pxt * 16 + gr + 8], p8);
            }
        }
        __syncthreads();   // D reads + sS accumulation done

        // ---- sigmoid (warps 0-1) + TIR stages raw D into sDt ----
        {
            if (t < 64) sA[t] = 1.f / (1.f + expf(-(sS[t] + bt2v)));
            if (br == 1) {
                float* sDt = (float*)smc;           // [o*33 + px]
                #pragma unroll
                for (int nt = 0; nt < 4; nt++) {
                    int c0 = nt * 8 + 2 * q;
                    int r0 = rbase + gr, r1 = r0 + 8;
                    sDt[r0 * 33 + c0]     = acc[nt][0];
                    sDt[r0 * 33 + c0 + 1] = acc[nt][1];
                    sDt[r1 * 33 + c0]     = acc[nt][2];
                    sDt[r1 * 33 + c0 + 1] = acc[nt][3];
                }
            }
        }
        __syncthreads();

        // ---- fuse + store (RGB warps): out = aR*Dr + aT*Dt ----
        if (br == 0) {
            const float* sDt = (const float*)smc;
            float* go = out + (size_t)(b * HALF) * NPIX + pix0;
            #pragma unroll
            for (int nt = 0; nt < 4; nt++) {
                int c0 = nt * 8 + 2 * q;
                int r0 = rbase + gr, r1 = r0 + 8;
                float aR0 = sA[c0], aR1 = sA[c0 + 1];
                float aT0 = sA[32 + c0], aT1 = sA[32 + c0 + 1];
                float2 v0, v1;
                v0.x = aR0 * acc[nt][0] + aT0 * sDt[r0 * 33 + c0];
                v0.y = aR1 * acc[nt][1] + aT1 * sDt[r0 * 33 + c0 + 1];
                v1.x = aR0 * acc[nt][2] + aT0 * sDt[r1 * 33 + c0];
                v1.y = aR1 * acc[nt][3] + aT1 * sDt[r1 * 33 + c0 + 1];
                *(float2*)(go + (size_t)r0 * NPIX + c0) = v0;
                *(float2*)(go + (size_t)r1 * NPIX + c0) = v1;
            }
        }

        // ---- rotate x double-buffer ----
        if (more) {
            #pragma unroll
            for (int j = 0; j < 8; j++) { xa[j] = na[j]; xb[j] = nb[j]; }
        }
    }
}

extern "C" void kernel_launch(void* const* d_in, const int* in_sizes, int n_in,
                              void* d_out, int out_size) {
    const float* x    = (const float*)d_in[0];
    const float* Wg   = (const float*)d_in[1];
    const float* bg   = (const float*)d_in[2];
    const float* Wrgb = (const float*)d_in[3];
    const float* brgb = (const float*)d_in[4];
    const float* Wtir = (const float*)d_in[5];
    const float* btir = (const float*)d_in[6];
    const float* Wt1  = (const float*)d_in[7];
    const float* bt1  = (const float*)d_in[8];
    const float* Wt2  = (const float*)d_in[9];
    const float* bt2  = (const float*)d_in[10];
    float* out = (float*)d_out;

    gate_pool<<<BDIM * CDIM, 256>>>(x);
    gate_select<<<1, 256>>>(Wg, bg);

    cudaFuncSetAttribute(moe_expert, cudaFuncAttributeMaxDynamicSharedMemorySize, SMEM_BYTES);
    dim3 grid(37, BDIM);
    moe_expert<<<grid, 512, SMEM_BYTES>>>(x, Wrgb, brgb, Wtir, btir,
                                          Wt1, bt1, Wt2, bt2, out);
}

// round 6
// speedup vs baseline: 2.7494x; 1.1935x over previous
#include <cuda_runtime.h>
#include <cstdint>
#include <math.h>

#define E_EXPERTS 5
#define CDIM      256
#define HALF      128
#define QUART     64
#define BDIM      8
#define NPIX      6400
#define PIX       32

typedef uint32_t u32;
typedef uint16_t u16;

__device__ int   g_expert[BDIM];
__device__ float g_pooled[BDIM * CDIM];

// ---------- fp16 helpers ----------
__device__ __forceinline__ u16 to_f16(float f) {
    u16 h; asm("cvt.rn.f16.f32 %0, %1;" : "=h"(h) : "f"(f)); return h;
}
__device__ __forceinline__ float from_f16(u16 h) {
    float f; asm("cvt.f32.f16 %0, %1;" : "=f"(f) : "h"(h)); return f;
}
__device__ __forceinline__ float rtne_f16(float f) {
    float r;
    asm("{\n .reg .b16 h;\n cvt.rn.f16.f32 h, %1;\n cvt.f32.f16 %0, h;\n}" : "=f"(r) : "f"(f));
    return r;
}
// packs (lo -> low half, hi -> high half), same convention as validated bf16 helper
__device__ __forceinline__ u32 pack_f16x2(float lo, float hi) {
    u32 r; asm("cvt.rn.f16x2.f32 %0, %1, %2;" : "=r"(r) : "f"(hi), "f"(lo)); return r;
}

// ---------- warp mma: D(16x8,f32) += A(16x16,f16 row) * B(16x8,f16 col) ----------
__device__ __forceinline__ void mma_f16(float* d, const u32* a, const u32* b) {
    asm volatile("mma.sync.aligned.m16n8k16.row.col.f32.f16.f16.f32 "
        "{%0,%1,%2,%3},{%4,%5,%6,%7},{%8,%9},{%0,%1,%2,%3};"
        : "+f"(d[0]), "+f"(d[1]), "+f"(d[2]), "+f"(d[3])
        : "r"(a[0]), "r"(a[1]), "r"(a[2]), "r"(a[3]), "r"(b[0]), "r"(b[1]));
}

// ======================= gate kernels =======================
__global__ void __launch_bounds__(256) gate_pool(const float* __restrict__ x) {
    int bc = blockIdx.x;
    const float4* p4 = (const float4*)(x + (size_t)bc * NPIX);
    float s = 0.f;
    for (int i = threadIdx.x; i < NPIX / 4; i += 256) {
        float4 v = __ldg(p4 + i);
        s += (v.x + v.y) + (v.z + v.w);
    }
    __shared__ float red[32];
    #pragma unroll
    for (int o = 16; o; o >>= 1) s += __shfl_down_sync(0xffffffffu, s, o);
    if ((threadIdx.x & 31) == 0) red[threadIdx.x >> 5] = s;
    __syncthreads();
    if (threadIdx.x < 32) {
        float v = (threadIdx.x < 8) ? red[threadIdx.x] : 0.f;
        #pragma unroll
        for (int o = 4; o; o >>= 1) v += __shfl_down_sync(0xffffffffu, v, o);
        if (threadIdx.x == 0) g_pooled[bc] = v * (1.0f / (float)NPIX);
    }
}

__global__ void __launch_bounds__(256) gate_select(const float* __restrict__ Wg,
                                                   const float* __restrict__ bg) {
    int w = threadIdx.x >> 5, lane = threadIdx.x & 31;
    if (w >= BDIM) return;
    float best = -1e30f; int bi = 0;
    for (int e = 0; e < E_EXPERTS; e++) {
        float s = 0.f;
        for (int c = lane; c < CDIM; c += 32) s += g_pooled[w * CDIM + c] * Wg[e * CDIM + c];
        #pragma unroll
        for (int o = 16; o; o >>= 1) s += __shfl_down_sync(0xffffffffu, s, o);
        s += bg[e];
        s = __shfl_sync(0xffffffffu, s, 0);
        if (s > best) { best = s; bi = e; }
    }
    if (lane == 0) g_expert[w] = bi;
}

// ======================= smem layout (bytes) =======================
// Split-row fp16 layout: K=128 in 2 planes of 64 elems; row = 64 f16 = 128B
// padded to 144B (conflict-free fragment LDS).
// Region A (18432B), time-multiplexed per tile:
//   phase 1: xhi(br) = br*9216 (2 planes x 32 px-rows x 144B)
//   phase 2: Dhi (same addressing)
//   phase 3: sDt fp32 [o*33+px] (16896B)
// W  : W_OFF + (br*2+hl)*36864  (hi/lo, 2 planes x 128 rows x 144B)
// W1 : W1_OFF + hl*18432        (hi/lo, 2 planes x 64 rows x 144B)
// sA : 64 f32 @ SA_OFF;  sS : 64 f32 @ SS_OFF
#define W_OFF    18432
#define W1_OFF   165888
#define SA_OFF   202752
#define SS_OFF   203008
#define SMEM_BYTES 203264

__global__ void __launch_bounds__(512, 1) moe_expert(
    const float* __restrict__ x,
    const float* __restrict__ Wrgb, const float* __restrict__ brgb,
    const float* __restrict__ Wtir, const float* __restrict__ btir,
    const float* __restrict__ Wt1,  const float* __restrict__ bt1,
    const float* __restrict__ Wt2,  const float* __restrict__ bt2,
    float* __restrict__ out)
{
    extern __shared__ char smc[];
    float* sA = (float*)(smc + SA_OFF);
    float* sS = (float*)(smc + SS_OFF);

    const int t    = threadIdx.x;
    const int w    = t >> 5;
    const int lane = t & 31;
    const int gr   = lane >> 2;
    const int q    = lane & 3;
    const int br   = w >> 3;            // branch: 0=RGB, 1=TIR
    const int msub = w & 7;
    const int rbase = msub * 16;        // GEMM1 o-rows

    const int b = blockIdx.y;
    const int e = g_expert[b];

    // 18 blocks/batch: 2x12 + 16x11 = 200 tiles (single wave: 144 blocks)
    const int ib    = blockIdx.x;
    const int tile0 = ib < 2 ? ib * 12 : 24 + (ib - 2) * 11;
    const int tcnt  = ib < 2 ? 12 : 11;

    // ---- hoisted per-thread constants ----
    const float bz0 = __ldg((br ? btir : brgb) + e * HALF + rbase + gr);
    const float bz1 = __ldg((br ? btir : brgb) + e * HALF + rbase + gr + 8);
    const int   pxt   = msub >> 2;      // GEMM2 px tile
    const int   npair = msub & 3;       // GEMM2 n8-pair
    float w2x[2], w2y[2], b1x[2], b1y[2];
    #pragma unroll
    for (int j = 0; j < 2; j++) {
        int m0 = (npair * 2 + j) * 8 + 2 * q;
        w2x[j] = __ldg(Wt2 + e * QUART + m0);
        w2y[j] = __ldg(Wt2 + e * QUART + m0 + 1);
        b1x[j] = __ldg(bt1 + e * QUART + m0);
        b1y[j] = __ldg(bt1 + e * QUART + m0 + 1);
    }
    const float bt2v = __ldg(bt2 + e);

    // ---------------- prologue: W, W1 -> fp16 hi/lo in smem ----------------
    #pragma unroll
    for (int br2 = 0; br2 < 2; br2++) {
        const float* gW = (br2 ? Wtir : Wrgb) + (size_t)e * HALF * HALF;
        char* bh = smc + W_OFF + (br2 * 2) * 36864;
        char* bl = bh + 36864;
        #pragma unroll 4
        for (int it = 0; it < 16; it++) {
            int lin = it * 512 + t;            // 8192 = 128 o x 64 c-pairs
            int o = lin >> 6, c0 = (lin & 63) * 2;
            float2 v = __ldg((const float2*)(gW + o * 128 + c0));
            float h0 = rtne_f16(v.x), h1 = rtne_f16(v.y);
            int addr = (c0 >> 6) * 18432 + o * 144 + (c0 & 63) * 2;
            *(u32*)(bh + addr) = pack_f16x2(h0, h1);
            *(u32*)(bl + addr) = pack_f16x2(v.x - h0, v.y - h1);
        }
    }
    {
        const float* g1 = Wt1 + (size_t)e * QUART * HALF;
        char* bh = smc + W1_OFF;
        char* bl = bh + 18432;
        #pragma unroll 4
        for (int it = 0; it < 8; it++) {
            int lin = it * 512 + t;            // 4096 = 64 m x 64 c-pairs
            int m = lin >> 6, c0 = (lin & 63) * 2;
            float2 v = __ldg((const float2*)(g1 + m * 128 + c0));
            float h0 = rtne_f16(v.x), h1 = rtne_f16(v.y);
            int addr = (c0 >> 6) * 9216 + m * 144 + (c0 & 63) * 2;
            *(u32*)(bh + addr) = pack_f16x2(h0, h1);
            *(u32*)(bl + addr) = pack_f16x2(v.x - h0, v.y - h1);
        }
    }

    // ---- x double-buffer: thread = (channel-pair, px-quarter) ----
    const int cp  = t & 127, c0x = 2 * cp, pxq = t >> 7;     // pxq 0..3
    const int brx = c0x >> 7;
    const int plx = (c0x & 64) ? 4608 : 0;
    const int cin = (c0x & 63) * 2;
    const float* gx0 = x + ((size_t)(b * CDIM + c0x)) * NPIX + pxq * 8;

    float xa[8], xb[8];
    {
        const float* g = gx0 + tile0 * PIX;
        *(float4*)xa       = __ldg((const float4*)g);
        *(float4*)(xa + 4) = __ldg((const float4*)(g + 4));
        *(float4*)xb       = __ldg((const float4*)(g + NPIX));
        *(float4*)(xb + 4) = __ldg((const float4*)(g + NPIX + 4));
    }

    for (int tt = 0; tt < tcnt; tt++) {
        const int pix0 = (tile0 + tt) * PIX;
        __syncthreads();   // region A free

        // ---- write xhi fp16 tile from regs ----
        {
            char* bh = smc + brx * 9216 + plx;
            #pragma unroll
            for (int j = 0; j < 8; j++) {
                int px = pxq * 8 + j;
                *(u32*)(bh + px * 144 + cin) = pack_f16x2(xa[j], xb[j]);
            }
        }
        __syncthreads();

        // ---- prefetch next tile's x (hidden under GEMMs) ----
        float na[8], nb[8];
        const bool more = (tt + 1 < tcnt);
        if (more) {
            const float* g = gx0 + pix0 + PIX;
            *(float4*)na       = __ldg((const float4*)g);
            *(float4*)(na + 4) = __ldg((const float4*)(g + 4));
            *(float4*)nb       = __ldg((const float4*)(g + NPIX));
            *(float4*)(nb + 4) = __ldg((const float4*)(g + NPIX + 4));
        }

        // ---- GEMM1: acc = Whi@xhi + Wlo@xhi (fp16 2-product) ----
        float acc[4][4];
        #pragma unroll
        for (int nt = 0; nt < 4; nt++)
            #pragma unroll
            for (int i = 0; i < 4; i++) acc[nt][i] = 0.f;

        // residual prefetch (L2-hot: whole tile just read)
        float2 rx0[4], rx1[4];
        {
            const float* gxr = x + ((size_t)(b * CDIM) + br * HALF) * NPIX + pix0;
            #pragma unroll
            for (int nt = 0; nt < 4; nt++) {
                int c0 = nt * 8 + 2 * q;
                rx0[nt] = __ldg((const float2*)(gxr + (size_t)(rbase + gr) * NPIX + c0));
                rx1[nt] = __ldg((const float2*)(gxr + (size_t)(rbase + gr + 8) * NPIX + c0));
            }
        }
        {
            const char* Ah = smc + W_OFF + (br * 2) * 36864;
            const char* Al = Ah + 36864;
            const char* Bh = smc + br * 9216;
            const int rb = (rbase + gr) * 144, rb8 = rb + 1152;
            #pragma unroll 4
            for (int kt = 0; kt < 8; kt++) {
                const int wp = (kt >> 2) * 18432 + (kt & 3) * 32 + q * 4;
                const int bp = (kt >> 2) * 4608  + (kt & 3) * 32 + q * 4;
                u32 ah[4], al[4], bh[4][2];
                ah[0] = *(const u32*)(Ah + wp + rb);
                ah[1] = *(const u32*)(Ah + wp + rb8);
                ah[2] = *(const u32*)(Ah + wp + rb + 16);
                ah[3] = *(const u32*)(Ah + wp + rb8 + 16);
                al[0] = *(const u32*)(Al + wp + rb);
                al[1] = *(const u32*)(Al + wp + rb8);
                al[2] = *(const u32*)(Al + wp + rb + 16);
                al[3] = *(const u32*)(Al + wp + rb8 + 16);
                #pragma unroll
                for (int nt = 0; nt < 4; nt++) {
                    int nb2 = (nt * 8 + gr) * 144;
                    bh[nt][0] = *(const u32*)(Bh + bp + nb2);
                    bh[nt][1] = *(const u32*)(Bh + bp + nb2 + 16);
                }
                #pragma unroll
                for (int nt = 0; nt < 4; nt++) {
                    mma_f16(acc[nt], ah, bh[nt]);
                    mma_f16(acc[nt], al, bh[nt]);
                }
            }
        }
        // epilogue: + residual + bias (exact fp32)
        #pragma unroll
        for (int nt = 0; nt < 4; nt++) {
            acc[nt][0] += rx0[nt].x + bz0;
            acc[nt][1] += rx0[nt].y + bz0;
            acc[nt][2] += rx1[nt].x + bz1;
            acc[nt][3] += rx1[nt].y + bz1;
        }
        __syncthreads();   // xhi reads done

        // ---- store Dhi fp16 (overwrites xhi); zero sS ----
        {
            char* Dh = smc + br * 9216;
            const int pl0 = (rbase & 64) ? 4608 : 0;
            const int in0 = ((rbase + gr) & 63) * 2;
            #pragma unroll
            for (int nt = 0; nt < 4; nt++) {
                int px0 = nt * 8 + 2 * q;
                #pragma unroll
                for (int i = 0; i < 4; i++) {
                    int px = px0 + (i & 1);
                    int in = in0 + ((i < 2) ? 0 : 16);
                    *(u16*)(Dh + pl0 + px * 144 + in) = to_f16(acc[nt][i]);
                }
            }
            if (t < 64) sS[t] = 0.f;
        }
        __syncthreads();

        // ---- GEMM2': h^T = Dhi@(W1hi+W1lo)^T ; fused attention reduction ----
        {
            float acc2[2][4];
            #pragma unroll
            for (int j = 0; j < 2; j++)
                #pragma unroll
                for (int i = 0; i < 4; i++) acc2[j][i] = 0.f;

            const char* A2 = smc + br * 9216;          // Dhi
            const char* B2h = smc + W1_OFF;            // W1 hi
            const char* B2l = B2h + 18432;             // W1 lo
            const int prb = (pxt * 16 + gr) * 144, prb8 = prb + 1152;
            #pragma unroll 4
            for (int kt = 0; kt < 8; kt++) {
                const int wpA = (kt >> 2) * 4608 + (kt & 3) * 32 + q * 4;
                const int wpB = (kt >> 2) * 9216 + (kt & 3) * 32 + q * 4;
                u32 ah[4], bh[2][2], bl[2][2];
                ah[0] = *(const u32*)(A2 + wpA + prb);
                ah[1] = *(const u32*)(A2 + wpA + prb8);
                ah[2] = *(const u32*)(A2 + wpA + prb + 16);
                ah[3] = *(const u32*)(A2 + wpA + prb8 + 16);
                #pragma unroll
                for (int j = 0; j < 2; j++) {
                    int nb2 = ((npair * 2 + j) * 8 + gr) * 144;
                    bh[j][0] = *(const u32*)(B2h + wpB + nb2);
                    bh[j][1] = *(const u32*)(B2h + wpB + nb2 + 16);
                    bl[j][0] = *(const u32*)(B2l + wpB + nb2);
                    bl[j][1] = *(const u32*)(B2l + wpB + nb2 + 16);
                }
                #pragma unroll
                for (int j = 0; j < 2; j++) {
                    mma_f16(acc2[j], ah, bh[j]);
                    mma_f16(acc2[j], ah, bl[j]);
                }
            }
            // fused attention partials: s[px] += w2[m]*relu(h + bt1)
            float p0 = 0.f, p8 = 0.f;
            #pragma unroll
            for (int j = 0; j < 2; j++) {
                p0 += w2x[j] * fmaxf(acc2[j][0] + b1x[j], 0.f)
                    + w2y[j] * fmaxf(acc2[j][1] + b1y[j], 0.f);
                p8 += w2x[j] * fmaxf(acc2[j][2] + b1x[j], 0.f)
                    + w2y[j] * fmaxf(acc2[j][3] + b1y[j], 0.f);
            }
            p0 += __shfl_xor_sync(0xffffffffu, p0, 1);
            p0 += __shfl_xor_sync(0xffffffffu, p0, 2);
            p8 += __shfl_xor_sync(0xffffffffu, p8, 1);
            p8 += __shfl_xor_sync(0xffffffffu, p8, 2);
            if (q == 0) {
                atomicAdd(&sS[br * 32 + pxt * 16 + gr], p0);
                atomicAdd(&sS[br * 32 + pxt * 16 + gr + 8], p8);
            }
        }
        __syncthreads();   // D reads + sS done

        // ---- sigmoid + TIR stages raw D into sDt ----
        {
            if (t < 64) sA[t] = 1.f / (1.f + expf(-(sS[t] + bt2v)));
            if (br == 1) {
                float* sDt = (float*)smc;           // [o*33 + px]
                #pragma unroll
                for (int nt = 0; nt < 4; nt++) {
                    int c0 = nt * 8 + 2 * q;
                    int r0 = rbase + gr, r1 = r0 + 8;
                    sDt[r0 * 33 + c0]     = acc[nt][0];
                    sDt[r0 * 33 + c0 + 1] = acc[nt][1];
                    sDt[r1 * 33 + c0]     = acc[nt][2];
                    sDt[r1 * 33 + c0 + 1] = acc[nt][3];
                }
            }
        }
        __syncthreads();

        // ---- fuse + store (RGB warps): out = aR*Dr + aT*Dt ----
        if (br == 0) {
            const float* sDt = (const float*)smc;
            float* go = out + (size_t)(b * HALF) * NPIX + pix0;
            #pragma unroll
            for (int nt = 0; nt < 4; nt++) {
                int c0 = nt * 8 + 2 * q;
                int r0 = rbase + gr, r1 = r0 + 8;
                float aR0 = sA[c0], aR1 = sA[c0 + 1];
                float aT0 = sA[32 + c0], aT1 = sA[32 + c0 + 1];
                float2 v0, v1;
                v0.x = aR0 * acc[nt][0] + aT0 * sDt[r0 * 33 + c0];
                v0.y = aR1 * acc[nt][1] + aT1 * sDt[r0 * 33 + c0 + 1];
                v1.x = aR0 * acc[nt][2] + aT0 * sDt[r1 * 33 + c0];
                v1.y = aR1 * acc[nt][3] + aT1 * sDt[r1 * 33 + c0 + 1];
                *(float2*)(go + (size_t)r0 * NPIX + c0) = v0;
                *(float2*)(go + (size_t)r1 * NPIX + c0) = v1;
            }
        }

        // ---- rotate x double-buffer ----
        if (more) {
            #pragma unroll
            for (int j = 0; j < 8; j++) { xa[j] = na[j]; xb[j] = nb[j]; }
        }
    }
}

extern "C" void kernel_launch(void* const* d_in, const int* in_sizes, int n_in,
                              void* d_out, int out_size) {
    const float* x    = (const float*)d_in[0];
    const float* Wg   = (const float*)d_in[1];
    const float* bg   = (const float*)d_in[2];
    const float* Wrgb = (const float*)d_in[3];
    const float* brgb = (const float*)d_in[4];
    const float* Wtir = (const float*)d_in[5];
    const float* btir = (const float*)d_in[6];
    const float* Wt1  = (const float*)d_in[7];
    const float* bt1  = (const float*)d_in[8];
    const float* Wt2  = (const float*)d_in[9];
    const float* bt2  = (const float*)d_in[10];
    float* out = (float*)d_out;

    gate_pool<<<BDIM * CDIM, 256>>>(x);
    gate_select<<<1, 256>>>(Wg, bg);

    cudaFuncSetAttribute(moe_expert, cudaFuncAttributeMaxDynamicSharedMemorySize, SMEM_BYTES);
    dim3 grid(18, BDIM);
    moe_expert<<<grid, 512, SMEM_BYTES>>>(x, Wrgb, brgb, Wtir, btir,
                                          Wt1, bt1, Wt2, bt2, out);
}

// round 7
// speedup vs baseline: 3.4636x; 1.2598x over previous
#include <cuda_runtime.h>
#include <cstdint>
#include <math.h>

#define E_EXPERTS 5
#define CDIM      256
#define HALF      128
#define QUART     64
#define BDIM      8
#define NPIX      6400
#define PIX       32

typedef uint32_t u32;
typedef uint16_t u16;

__device__ int   g_expert[BDIM];
__device__ float g_pooled[BDIM * CDIM];

// ---------- fp16 helpers ----------
__device__ __forceinline__ u16 to_f16(float f) {
    u16 h; asm("cvt.rn.f16.f32 %0, %1;" : "=h"(h) : "f"(f)); return h;
}
// packs (lo -> low half, hi -> high half)
__device__ __forceinline__ u32 pack_f16x2(float lo, float hi) {
    u32 r; asm("cvt.rn.f16x2.f32 %0, %1, %2;" : "=r"(r) : "f"(hi), "f"(lo)); return r;
}

// ---------- warp mma: D(16x8,f32) += A(16x16,f16 row) * B(16x8,f16 col) ----------
__device__ __forceinline__ void mma_f16(float* d, const u32* a, const u32* b) {
    asm volatile("mma.sync.aligned.m16n8k16.row.col.f32.f16.f16.f32 "
        "{%0,%1,%2,%3},{%4,%5,%6,%7},{%8,%9},{%0,%1,%2,%3};"
        : "+f"(d[0]), "+f"(d[1]), "+f"(d[2]), "+f"(d[3])
        : "r"(a[0]), "r"(a[1]), "r"(a[2]), "r"(a[3]), "r"(b[0]), "r"(b[1]));
}

// ======================= gate kernels =======================
__global__ void __launch_bounds__(320) gate_pool(const float* __restrict__ x) {
    int bc = blockIdx.x;
    const float4* p4 = (const float4*)(x + (size_t)bc * NPIX);
    float s = 0.f;
    #pragma unroll
    for (int k = 0; k < 5; k++) {             // 1600 float4 = 320 x 5 exactly
        float4 v = __ldg(p4 + k * 320 + threadIdx.x);
        s += (v.x + v.y) + (v.z + v.w);
    }
    __shared__ float red[10];
    #pragma unroll
    for (int o = 16; o; o >>= 1) s += __shfl_down_sync(0xffffffffu, s, o);
    if ((threadIdx.x & 31) == 0) red[threadIdx.x >> 5] = s;
    __syncthreads();
    if (threadIdx.x < 32) {
        float v = (threadIdx.x < 10) ? red[threadIdx.x] : 0.f;
        #pragma unroll
        for (int o = 8; o; o >>= 1) v += __shfl_down_sync(0xffffffffu, v, o);
        if (threadIdx.x == 0) g_pooled[bc] = v * (1.0f / (float)NPIX);
    }
}

__global__ void __launch_bounds__(256) gate_select(const float* __restrict__ Wg,
                                                   const float* __restrict__ bg) {
    int w = threadIdx.x >> 5, lane = threadIdx.x & 31;
    if (w >= BDIM) return;
    float best = -1e30f; int bi = 0;
    for (int e = 0; e < E_EXPERTS; e++) {
        float s = 0.f;
        for (int c = lane; c < CDIM; c += 32) s += g_pooled[w * CDIM + c] * Wg[e * CDIM + c];
        #pragma unroll
        for (int o = 16; o; o >>= 1) s += __shfl_down_sync(0xffffffffu, s, o);
        s += bg[e];
        s = __shfl_sync(0xffffffffu, s, 0);
        if (s > best) { best = s; bi = e; }
    }
    if (lane == 0) g_expert[w] = bi;
}

// ======================= smem layout (bytes) =======================
// Split-row fp16 layout: K=128 in 2 planes of 64 elems; row = 64 f16 = 128B
// padded to 144B (conflict-free fragment LDS: bank = 4*gr + q).
// Region A (18432B), time-multiplexed per tile:
//   phase 1: xhi(br) = br*9216 (2 planes x 32 px-rows x 144B)
//   phase 2: Dhi (same addressing)
//   phase 3: sDt fp32 [o*33+px] (16896B)
// W  : W_OFF + br*36864  (hi only, 2 planes x 128 rows x 144B)
// W1 : W1_OFF            (hi only, 2 planes x 64 rows x 144B)
// sA : 64 f32 @ SA_OFF;  sS : 64 f32 @ SS_OFF
#define W_OFF    18432
#define W1_OFF   92160
#define SA_OFF   110592
#define SS_OFF   110848
#define SMEM_BYTES 111104

__global__ void __launch_bounds__(512, 1) moe_expert(
    const float* __restrict__ x,
    const float* __restrict__ Wrgb, const float* __restrict__ brgb,
    const float* __restrict__ Wtir, const float* __restrict__ btir,
    const float* __restrict__ Wt1,  const float* __restrict__ bt1,
    const float* __restrict__ Wt2,  const float* __restrict__ bt2,
    float* __restrict__ out)
{
    extern __shared__ char smc[];
    float* sA = (float*)(smc + SA_OFF);
    float* sS = (float*)(smc + SS_OFF);

    const int t    = threadIdx.x;
    const int w    = t >> 5;
    const int lane = t & 31;
    const int gr   = lane >> 2;
    const int q    = lane & 3;
    const int br   = w >> 3;            // branch: 0=RGB, 1=TIR
    const int msub = w & 7;
    const int rbase = msub * 16;        // GEMM1 o-rows

    const int b = blockIdx.y;
    const int e = g_expert[b];

    // 18 blocks/batch: 2x12 + 16x11 = 200 tiles (single wave: 144 blocks)
    const int ib    = blockIdx.x;
    const int tile0 = ib < 2 ? ib * 12 : 24 + (ib - 2) * 11;
    const int tcnt  = ib < 2 ? 12 : 11;

    // ---- hoisted per-thread constants ----
    const float bz0 = __ldg((br ? btir : brgb) + e * HALF + rbase + gr);
    const float bz1 = __ldg((br ? btir : brgb) + e * HALF + rbase + gr + 8);
    const int   pxt   = msub >> 2;      // GEMM2 px tile
    const int   npair = msub & 3;       // GEMM2 n8-pair
    float w2x[2], w2y[2], b1x[2], b1y[2];
    #pragma unroll
    for (int j = 0; j < 2; j++) {
        int m0 = (npair * 2 + j) * 8 + 2 * q;
        w2x[j] = __ldg(Wt2 + e * QUART + m0);
        w2y[j] = __ldg(Wt2 + e * QUART + m0 + 1);
        b1x[j] = __ldg(bt1 + e * QUART + m0);
        b1y[j] = __ldg(bt1 + e * QUART + m0 + 1);
    }
    const float bt2v = __ldg(bt2 + e);

    // ---------------- prologue: W, W1 -> fp16 (hi) in smem ----------------
    #pragma unroll
    for (int br2 = 0; br2 < 2; br2++) {
        const float* gW = (br2 ? Wtir : Wrgb) + (size_t)e * HALF * HALF;
        char* bh = smc + W_OFF + br2 * 36864;
        #pragma unroll 4
        for (int it = 0; it < 16; it++) {
            int lin = it * 512 + t;            // 8192 = 128 o x 64 c-pairs
            int o = lin >> 6, c0 = (lin & 63) * 2;
            float2 v = __ldg((const float2*)(gW + o * 128 + c0));
            int addr = (c0 >> 6) * 18432 + o * 144 + (c0 & 63) * 2;
            *(u32*)(bh + addr) = pack_f16x2(v.x, v.y);
        }
    }
    {
        const float* g1 = Wt1 + (size_t)e * QUART * HALF;
        char* bh = smc + W1_OFF;
        #pragma unroll 4
        for (int it = 0; it < 8; it++) {
            int lin = it * 512 + t;            // 4096 = 64 m x 64 c-pairs
            int m = lin >> 6, c0 = (lin & 63) * 2;
            float2 v = __ldg((const float2*)(g1 + m * 128 + c0));
            int addr = (c0 >> 6) * 9216 + m * 144 + (c0 & 63) * 2;
            *(u32*)(bh + addr) = pack_f16x2(v.x, v.y);
        }
    }

    // ---- x double-buffer: thread = (channel-pair, px-quarter) ----
    const int cp  = t & 127, c0x = 2 * cp, pxq = t >> 7;     // pxq 0..3
    const int brx = c0x >> 7;
    const int plx = (c0x & 64) ? 4608 : 0;
    const int cin = (c0x & 63) * 2;
    const float* gx0 = x + ((size_t)(b * CDIM + c0x)) * NPIX + pxq * 8;

    float xa[8], xb[8];
    {
        const float* g = gx0 + tile0 * PIX;
        *(float4*)xa       = __ldg((const float4*)g);
        *(float4*)(xa + 4) = __ldg((const float4*)(g + 4));
        *(float4*)xb       = __ldg((const float4*)(g + NPIX));
        *(float4*)(xb + 4) = __ldg((const float4*)(g + NPIX + 4));
    }

    for (int tt = 0; tt < tcnt; tt++) {
        const int pix0 = (tile0 + tt) * PIX;
        __syncthreads();   // region A free

        // ---- write xhi fp16 tile from regs ----
        {
            char* bh = smc + brx * 9216 + plx;
            #pragma unroll
            for (int j = 0; j < 8; j++) {
                int px = pxq * 8 + j;
                *(u32*)(bh + px * 144 + cin) = pack_f16x2(xa[j], xb[j]);
            }
        }
        __syncthreads();

        // ---- prefetch next tile's x (hidden under GEMMs) ----
        float na[8], nb[8];
        const bool more = (tt + 1 < tcnt);
        if (more) {
            const float* g = gx0 + pix0 + PIX;
            *(float4*)na       = __ldg((const float4*)g);
            *(float4*)(na + 4) = __ldg((const float4*)(g + 4));
            *(float4*)nb       = __ldg((const float4*)(g + NPIX));
            *(float4*)(nb + 4) = __ldg((const float4*)(g + NPIX + 4));
        }

        // ---- GEMM1: acc = Whi@xhi (single product) ----
        float acc[4][4];
        #pragma unroll
        for (int nt = 0; nt < 4; nt++)
            #pragma unroll
            for (int i = 0; i < 4; i++) acc[nt][i] = 0.f;

        // residual prefetch (L2-hot: whole tile just read)
        float2 rx0[4], rx1[4];
        {
            const float* gxr = x + ((size_t)(b * CDIM) + br * HALF) * NPIX + pix0;
            #pragma unroll
            for (int nt = 0; nt < 4; nt++) {
                int c0 = nt * 8 + 2 * q;
                rx0[nt] = __ldg((const float2*)(gxr + (size_t)(rbase + gr) * NPIX + c0));
                rx1[nt] = __ldg((const float2*)(gxr + (size_t)(rbase + gr + 8) * NPIX + c0));
            }
        }
        {
            const char* Ah = smc + W_OFF + br * 36864;
            const char* Bh = smc + br * 9216;
            const int rb = (rbase + gr) * 144, rb8 = rb + 1152;
            #pragma unroll 4
            for (int kt = 0; kt < 8; kt++) {
                const int wp = (kt >> 2) * 18432 + (kt & 3) * 32 + q * 4;
                const int bp = (kt >> 2) * 4608  + (kt & 3) * 32 + q * 4;
                u32 ah[4], bh[4][2];
                ah[0] = *(const u32*)(Ah + wp + rb);
                ah[1] = *(const u32*)(Ah + wp + rb8);
                ah[2] = *(const u32*)(Ah + wp + rb + 16);
                ah[3] = *(const u32*)(Ah + wp + rb8 + 16);
                #pragma unroll
                for (int nt = 0; nt < 4; nt++) {
                    int nb2 = (nt * 8 + gr) * 144;
                    bh[nt][0] = *(const u32*)(Bh + bp + nb2);
                    bh[nt][1] = *(const u32*)(Bh + bp + nb2 + 16);
                }
                #pragma unroll
                for (int nt = 0; nt < 4; nt++)
                    mma_f16(acc[nt], ah, bh[nt]);
            }
        }
        // epilogue: + residual + bias (exact fp32)
        #pragma unroll
        for (int nt = 0; nt < 4; nt++) {
            acc[nt][0] += rx0[nt].x + bz0;
            acc[nt][1] += rx0[nt].y + bz0;
            acc[nt][2] += rx1[nt].x + bz1;
            acc[nt][3] += rx1[nt].y + bz1;
        }
        __syncthreads();   // xhi reads done

        // ---- store Dhi fp16 (overwrites xhi); zero sS ----
        {
            char* Dh = smc + br * 9216;
            const int pl0 = (rbase & 64) ? 4608 : 0;
            const int in0 = ((rbase + gr) & 63) * 2;
            #pragma unroll
            for (int nt = 0; nt < 4; nt++) {
                int px0 = nt * 8 + 2 * q;
                #pragma unroll
                for (int i = 0; i < 4; i++) {
                    int px = px0 + (i & 1);
                    int in = in0 + ((i < 2) ? 0 : 16);
                    *(u16*)(Dh + pl0 + px * 144 + in) = to_f16(acc[nt][i]);
                }
            }
            if (t < 64) sS[t] = 0.f;
        }
        __syncthreads();

        // ---- GEMM2': h^T = Dhi@W1hi^T ; fused attention reduction ----
        {
            float acc2[2][4];
            #pragma unroll
            for (int j = 0; j < 2; j++)
                #pragma unroll
                for (int i = 0; i < 4; i++) acc2[j][i] = 0.f;

            const char* A2 = smc + br * 9216;          // Dhi
            const char* B2h = smc + W1_OFF;            // W1 hi
            const int prb = (pxt * 16 + gr) * 144, prb8 = prb + 1152;
            #pragma unroll 4
            for (int kt = 0; kt < 8; kt++) {
                const int wpA = (kt >> 2) * 4608 + (kt & 3) * 32 + q * 4;
                const int wpB = (kt >> 2) * 9216 + (kt & 3) * 32 + q * 4;
                u32 ah[4], bh[2][2];
                ah[0] = *(const u32*)(A2 + wpA + prb);
                ah[1] = *(const u32*)(A2 + wpA + prb8);
                ah[2] = *(const u32*)(A2 + wpA + prb + 16);
                ah[3] = *(const u32*)(A2 + wpA + prb8 + 16);
                #pragma unroll
                for (int j = 0; j < 2; j++) {
                    int nb2 = ((npair * 2 + j) * 8 + gr) * 144;
                    bh[j][0] = *(const u32*)(B2h + wpB + nb2);
                    bh[j][1] = *(const u32*)(B2h + wpB + nb2 + 16);
                }
                #pragma unroll
                for (int j = 0; j < 2; j++)
                    mma_f16(acc2[j], ah, bh[j]);
            }
            // fused attention partials: s[px] += w2[m]*relu(h + bt1)
            float p0 = 0.f, p8 = 0.f;
            #pragma unroll
            for (int j = 0; j < 2; j++) {
                p0 += w2x[j] * fmaxf(acc2[j][0] + b1x[j], 0.f)
                    + w2y[j] * fmaxf(acc2[j][1] + b1y[j], 0.f);
                p8 += w2x[j] * fmaxf(acc2[j][2] + b1x[j], 0.f)
                    + w2y[j] * fmaxf(acc2[j][3] + b1y[j], 0.f);
            }
            p0 += __shfl_xor_sync(0xffffffffu, p0, 1);
            p0 += __shfl_xor_sync(0xffffffffu, p0, 2);
            p8 += __shfl_xor_sync(0xffffffffu, p8, 1);
            p8 += __shfl_xor_sync(0xffffffffu, p8, 2);
            if (q == 0) {
                atomicAdd(&sS[br * 32 + pxt * 16 + gr], p0);
                atomicAdd(&sS[br * 32 + pxt * 16 + gr + 8], p8);
            }
        }
        __syncthreads();   // D reads + sS done

        // ---- sigmoid + TIR stages raw D into sDt ----
        {
            if (t < 64) sA[t] = 1.f / (1.f + expf(-(sS[t] + bt2v)));
            if (br == 1) {
                float* sDt = (float*)smc;           // [o*33 + px]
                #pragma unroll
                for (int nt = 0; nt < 4; nt++) {
                    int c0 = nt * 8 + 2 * q;
                    int r0 = rbase + gr, r1 = r0 + 8;
                    sDt[r0 * 33 + c0]     = acc[nt][0];
                    sDt[r0 * 33 + c0 + 1] = acc[nt][1];
                    sDt[r1 * 33 + c0]     = acc[nt][2];
                    sDt[r1 * 33 + c0 + 1] = acc[nt][3];
                }
            }
        }
        __syncthreads();

        // ---- fuse + store (RGB warps): out = aR*Dr + aT*Dt ----
        if (br == 0) {
            const float* sDt = (const float*)smc;
            float* go = out + (size_t)(b * HALF) * NPIX + pix0;
            #pragma unroll
            for (int nt = 0; nt < 4; nt++) {
                int c0 = nt * 8 + 2 * q;
                int r0 = rbase + gr, r1 = r0 + 8;
                float aR0 = sA[c0], aR1 = sA[c0 + 1];
                float aT0 = sA[32 + c0], aT1 = sA[32 + c0 + 1];
                float2 v0, v1;
                v0.x = aR0 * acc[nt][0] + aT0 * sDt[r0 * 33 + c0];
                v0.y = aR1 * acc[nt][1] + aT1 * sDt[r0 * 33 + c0 + 1];
                v1.x = aR0 * acc[nt][2] + aT0 * sDt[r1 * 33 + c0];
                v1.y = aR1 * acc[nt][3] + aT1 * sDt[r1 * 33 + c0 + 1];
                *(float2*)(go + (size_t)r0 * NPIX + c0) = v0;
                *(float2*)(go + (size_t)r1 * NPIX + c0) = v1;
            }
        }

        // ---- rotate x double-buffer ----
        if (more) {
            #pragma unroll
            for (int j = 0; j < 8; j++) { xa[j] = na[j]; xb[j] = nb[j]; }
        }
    }
}

extern "C" void kernel_launch(void* const* d_in, const int* in_sizes, int n_in,
                              void* d_out, int out_size) {
    const float* x    = (const float*)d_in[0];
    const float* Wg   = (const float*)d_in[1];
    const float* bg   = (const float*)d_in[2];
    const float* Wrgb = (const float*)d_in[3];
    const float* brgb = (const float*)d_in[4];
    const float* Wtir = (const float*)d_in[5];
    const float* btir = (const float*)d_in[6];
    const float* Wt1  = (const float*)d_in[7];
    const float* bt1  = (const float*)d_in[8];
    const float* Wt2  = (const float*)d_in[9];
    const float* bt2  = (const float*)d_in[10];
    float* out = (float*)d_out;

    gate_pool<<<BDIM * CDIM, 320>>>(x);
    gate_select<<<1, 256>>>(Wg, bg);

    cudaFuncSetAttribute(moe_expert, cudaFuncAttributeMaxDynamicSharedMemorySize, SMEM_BYTES);
    dim3 grid(18, BDIM);
    moe_expert<<<grid, 512, SMEM_BYTES>>>(x, Wrgb, brgb, Wtir, btir,
                                          Wt1, bt1, Wt2, bt2, out);
}